// round 2
// baseline (speedup 1.0000x reference)
#include <cuda_runtime.h>
#include <cuda_bf16.h>
#include <math.h>

#define SQ 4096
#define HID 2048
#define NH 8
#define NKV 4
#define HD 256
#define FFI 8192

// ---------------- scratch (device globals; no runtime allocation) ----------------
__device__ float g_xn[(size_t)SQ * HID];        // rmsnorm output (reused)
__device__ float g_q[(size_t)SQ * NH * HD];
__device__ float g_k[(size_t)SQ * NKV * HD];
__device__ float g_v[(size_t)SQ * NKV * HD];
__device__ float g_attn[(size_t)SQ * NH * HD];
__device__ float g_h1[(size_t)SQ * HID];        // hidden after attn residual
__device__ float g_gate[(size_t)SQ * FFI];
__device__ float g_up[(size_t)SQ * FFI];

// ---------------- RMSNorm ----------------
__device__ __forceinline__ float warp_red_sum(float v) {
    #pragma unroll
    for (int o = 16; o > 0; o >>= 1) v += __shfl_xor_sync(0xffffffffu, v, o);
    return v;
}

__global__ void rmsnorm_kernel(const float* __restrict__ x, const float* __restrict__ w,
                               float* __restrict__ out) {
    int row = blockIdx.x;
    int tid = threadIdx.x;
    const float* xr = x + (size_t)row * HID;
    float s = 0.f;
    for (int i = tid; i < HID; i += 256) { float v = xr[i]; s += v * v; }
    __shared__ float red[8];
    __shared__ float s_inv;
    s = warp_red_sum(s);
    if ((tid & 31) == 0) red[tid >> 5] = s;
    __syncthreads();
    if (tid == 0) {
        float t = 0.f;
        #pragma unroll
        for (int i = 0; i < 8; i++) t += red[i];
        s_inv = rsqrtf(t / (float)HID + 1e-6f);
    }
    __syncthreads();
    float inv = s_inv;
    float* orow = out + (size_t)row * HID;
    for (int i = tid; i < HID; i += 256) orow[i] = xr[i] * inv * w[i];
}

// ---------------- SGEMM 128x128x8, 8x8 micro-tile, optional residual ----------------
__global__ __launch_bounds__(256) void sgemm_kernel(
    const float* __restrict__ A, const float* __restrict__ B,
    const float* __restrict__ Cres, float* __restrict__ C,
    int M, int N, int K) {
    __shared__ float As[8][128];
    __shared__ float Bs[8][128];
    int bx = blockIdx.x, by = blockIdx.y;
    int tid = threadIdx.x;
    int arow = tid >> 1;            // 0..127
    int acol = (tid & 1) * 4;       // 0 or 4
    int brow = tid >> 5;            // 0..7
    int bcol = (tid & 31) * 4;      // 0..124
    int tx = tid & 15, ty = tid >> 4;
    const float* Ap = A + (size_t)(by * 128) * K;
    const float* Bp = B + (size_t)bx * 128;
    float acc[8][8] = {};
    for (int k0 = 0; k0 < K; k0 += 8) {
        float4 av = *(const float4*)(Ap + (size_t)arow * K + k0 + acol);
        As[acol + 0][arow] = av.x;
        As[acol + 1][arow] = av.y;
        As[acol + 2][arow] = av.z;
        As[acol + 3][arow] = av.w;
        *(float4*)&Bs[brow][bcol] = *(const float4*)(Bp + (size_t)(k0 + brow) * N + bcol);
        __syncthreads();
        #pragma unroll
        for (int k = 0; k < 8; k++) {
            float4 a0 = *(float4*)&As[k][ty * 8];
            float4 a1 = *(float4*)&As[k][ty * 8 + 4];
            float4 b0 = *(float4*)&Bs[k][tx * 8];
            float4 b1 = *(float4*)&Bs[k][tx * 8 + 4];
            float af[8] = {a0.x, a0.y, a0.z, a0.w, a1.x, a1.y, a1.z, a1.w};
            float bf[8] = {b0.x, b0.y, b0.z, b0.w, b1.x, b1.y, b1.z, b1.w};
            #pragma unroll
            for (int i = 0; i < 8; i++)
                #pragma unroll
                for (int j = 0; j < 8; j++) acc[i][j] += af[i] * bf[j];
        }
        __syncthreads();
    }
    #pragma unroll
    for (int i = 0; i < 8; i++) {
        size_t r = (size_t)(by * 128 + ty * 8 + i);
        float* crow = C + r * N + bx * 128 + tx * 8;
        const float* rrow = Cres ? (Cres + r * N + bx * 128 + tx * 8) : nullptr;
        #pragma unroll
        for (int j = 0; j < 8; j += 4) {
            float4 o;
            o.x = acc[i][j + 0]; o.y = acc[i][j + 1];
            o.z = acc[i][j + 2]; o.w = acc[i][j + 3];
            if (rrow) {
                float4 rv = *(const float4*)(rrow + j);
                o.x += rv.x; o.y += rv.y; o.z += rv.z; o.w += rv.w;
            }
            *(float4*)(crow + j) = o;
        }
    }
}

// ---------------- RoPE (in-place on g_q / g_k) ----------------
__global__ void rope_kernel(const int* __restrict__ pos_ids) {
    int idx = blockIdx.x * 256 + threadIdx.x;
    const int total = SQ * (NH + NKV) * 128;
    if (idx >= total) return;
    int j = idx & 127;
    int h = (idx >> 7) % (NH + NKV);
    int s = idx / (128 * (NH + NKV));
    // match reference: inv_freq in fp32, angle = fp32(pos * inv), accurate trig on that angle
    float inv = (float)(1.0 / pow(10000.0, (double)j / 128.0));
    float angf = (float)pos_ids[s] * inv;
    double ang = (double)angf;
    float c = (float)cos(ang);
    float sn = (float)sin(ang);
    float* base = (h < NH) ? (g_q + (size_t)s * (NH * HD) + h * HD)
                           : (g_k + (size_t)s * (NKV * HD) + (h - NH) * HD);
    float x0 = base[j], x1 = base[j + 128];
    base[j]       = x0 * c - x1 * sn;
    base[j + 128] = x1 * c + x0 * sn;
}

// ---------------- Flash attention: 64x64 tiles, online softmax ----------------
// smem: Qs[256][64] (Q^T, pre-scaled), Ks[256][64] (K^T) reused as Vs[64][256],
//       Ss[64][65] (padded), mrow/lrow/srow/mk[64]
#define ATTN_SMEM_FLOATS (256 * 64 + 256 * 64 + 64 * 65 + 4 * 64)
#define ATTN_SMEM_BYTES (ATTN_SMEM_FLOATS * sizeof(float))

__global__ __launch_bounds__(128) void attn_kernel(const int* __restrict__ amask) {
    extern __shared__ float sm[];
    float* Qs = sm;                    // [256][64]
    float* Ks = Qs + 256 * 64;         // [256][64]  (later Vs[64][256])
    float* Ss = Ks + 256 * 64;         // [64][65]
    float* mrow = Ss + 64 * 65;
    float* lrow = mrow + 64;
    float* srow = lrow + 64;
    float* mk = srow + 64;

    const int mt = blockIdx.x;         // query tile
    const int h = blockIdx.y;          // head
    const int m0 = mt * 64;
    const int kvh = h >> 1;            // GQA group of 2
    const int tid = threadIdx.x;
    const int ty = tid >> 3;           // 0..15
    const int tx = tid & 7;            // 0..7

    // load Q^T, pre-scaled by HD^-0.5 = 1/16
    for (int idx = tid; idx < 64 * 64; idx += 128) {
        int i = idx & 63, d4 = idx >> 6;
        float4 qv = *(const float4*)(g_q + (size_t)(m0 + i) * (NH * HD) + h * HD + d4 * 4);
        Qs[(d4 * 4 + 0) * 64 + i] = qv.x * 0.0625f;
        Qs[(d4 * 4 + 1) * 64 + i] = qv.y * 0.0625f;
        Qs[(d4 * 4 + 2) * 64 + i] = qv.z * 0.0625f;
        Qs[(d4 * 4 + 3) * 64 + i] = qv.w * 0.0625f;
    }
    if (tid < 64) { mrow[tid] = -1e30f; lrow[tid] = 0.f; }
    float acc[4][32];
    #pragma unroll
    for (int a = 0; a < 4; a++)
        #pragma unroll
        for (int w = 0; w < 32; w++) acc[a][w] = 0.f;
    __syncthreads();

    for (int jt = 0; jt <= mt; jt++) {
        int n0 = jt * 64;
        // load K^T
        for (int idx = tid; idx < 64 * 64; idx += 128) {
            int c = idx & 63, d4 = idx >> 6;
            float4 kv4 = *(const float4*)(g_k + (size_t)(n0 + c) * (NKV * HD) + kvh * HD + d4 * 4);
            Ks[(d4 * 4 + 0) * 64 + c] = kv4.x;
            Ks[(d4 * 4 + 1) * 64 + c] = kv4.y;
            Ks[(d4 * 4 + 2) * 64 + c] = kv4.z;
            Ks[(d4 * 4 + 3) * 64 + c] = kv4.w;
        }
        if (tid < 64) mk[tid] = (amask[n0 + tid] > 0) ? 0.f : -1e30f;
        __syncthreads();

        // S = Q K^T : each thread rows {ty+16a}, cols {tx*8+b}
        float sreg[4][8];
        #pragma unroll
        for (int a = 0; a < 4; a++)
            #pragma unroll
            for (int b = 0; b < 8; b++) sreg[a][b] = 0.f;
        #pragma unroll 8
        for (int k = 0; k < 256; k++) {
            float a0 = Qs[k * 64 + ty];
            float a1 = Qs[k * 64 + ty + 16];
            float a2 = Qs[k * 64 + ty + 32];
            float a3 = Qs[k * 64 + ty + 48];
            float4 b0 = *(float4*)&Ks[k * 64 + tx * 8];
            float4 b1 = *(float4*)&Ks[k * 64 + tx * 8 + 4];
            float bv[8] = {b0.x, b0.y, b0.z, b0.w, b1.x, b1.y, b1.z, b1.w};
            #pragma unroll
            for (int b = 0; b < 8; b++) {
                sreg[0][b] += a0 * bv[b];
                sreg[1][b] += a1 * bv[b];
                sreg[2][b] += a2 * bv[b];
                sreg[3][b] += a3 * bv[b];
            }
        }
        // mask + store transposed (Ss[c][i], padded row 65)
        #pragma unroll
        for (int a = 0; a < 4; a++)
            #pragma unroll
            for (int b = 0; b < 8; b++) {
                int i = ty + 16 * a, c = tx * 8 + b;
                float v = sreg[a][b] + mk[c];
                if (jt == mt && (n0 + c) > (m0 + i)) v = -1e30f;
                Ss[c * 65 + i] = v;
            }
        __syncthreads();

        // online softmax for row i (threads 0..63); others load V into Ks region
        if (tid < 64) {
            int i = tid;
            float mold = mrow[i];
            float mx = mold;
            #pragma unroll 8
            for (int c = 0; c < 64; c++) mx = fmaxf(mx, Ss[c * 65 + i]);
            float sum = 0.f;
            #pragma unroll 8
            for (int c = 0; c < 64; c++) {
                float p = expf(Ss[c * 65 + i] - mx);
                Ss[c * 65 + i] = p;
                sum += p;
            }
            float sc = expf(mold - mx);
            lrow[i] = lrow[i] * sc + sum;
            mrow[i] = mx;
            srow[i] = sc;
        }
        float* Vs = Ks;  // reuse K buffer as V[c][d]
        for (int idx = tid; idx < 64 * 64; idx += 128) {
            int c = idx >> 6, d4 = idx & 63;
            *(float4*)&Vs[c * 256 + d4 * 4] =
                *(const float4*)(g_v + (size_t)(n0 + c) * (NKV * HD) + kvh * HD + d4 * 4);
        }
        __syncthreads();

        // O = O*scale + P @ V : thread rows {ty+16a}, dims {tx*4 + 32w + 0..3}
        #pragma unroll
        for (int a = 0; a < 4; a++) {
            float scl = srow[ty + 16 * a];
            #pragma unroll
            for (int w = 0; w < 32; w++) acc[a][w] *= scl;
        }
        #pragma unroll 4
        for (int c = 0; c < 64; c++) {
            float p0 = Ss[c * 65 + ty];
            float p1 = Ss[c * 65 + ty + 16];
            float p2 = Ss[c * 65 + ty + 32];
            float p3 = Ss[c * 65 + ty + 48];
            #pragma unroll
            for (int w = 0; w < 8; w++) {
                float4 vv = *(float4*)&Vs[c * 256 + tx * 4 + w * 32];
                acc[0][w * 4 + 0] += p0 * vv.x; acc[0][w * 4 + 1] += p0 * vv.y;
                acc[0][w * 4 + 2] += p0 * vv.z; acc[0][w * 4 + 3] += p0 * vv.w;
                acc[1][w * 4 + 0] += p1 * vv.x; acc[1][w * 4 + 1] += p1 * vv.y;
                acc[1][w * 4 + 2] += p1 * vv.z; acc[1][w * 4 + 3] += p1 * vv.w;
                acc[2][w * 4 + 0] += p2 * vv.x; acc[2][w * 4 + 1] += p2 * vv.y;
                acc[2][w * 4 + 2] += p2 * vv.z; acc[2][w * 4 + 3] += p2 * vv.w;
                acc[3][w * 4 + 0] += p3 * vv.x; acc[3][w * 4 + 1] += p3 * vv.y;
                acc[3][w * 4 + 2] += p3 * vv.z; acc[3][w * 4 + 3] += p3 * vv.w;
            }
        }
        __syncthreads();
    }

    // normalize + write
    #pragma unroll
    for (int a = 0; a < 4; a++) {
        int i = ty + 16 * a;
        float invl = 1.f / lrow[i];
        #pragma unroll
        for (int w = 0; w < 8; w++) {
            float4 o;
            o.x = acc[a][w * 4 + 0] * invl;
            o.y = acc[a][w * 4 + 1] * invl;
            o.z = acc[a][w * 4 + 2] * invl;
            o.w = acc[a][w * 4 + 3] * invl;
            *(float4*)(g_attn + (size_t)(m0 + i) * (NH * HD) + h * HD + tx * 4 + w * 32) = o;
        }
    }
}

// ---------------- gelu(gate) * up, in place into g_gate ----------------
__device__ __forceinline__ float gelu_tanh(float x) {
    float x3 = x * x * x;
    return 0.5f * x * (1.f + tanhf(0.7978845608028654f * (x + 0.044715f * x3)));
}

__global__ void gelumul_kernel() {
    size_t idx = (size_t)blockIdx.x * 256 + threadIdx.x;
    const size_t n4 = (size_t)SQ * FFI / 4;
    if (idx >= n4) return;
    float4 g = ((const float4*)g_gate)[idx];
    float4 u = ((const float4*)g_up)[idx];
    g.x = gelu_tanh(g.x) * u.x;
    g.y = gelu_tanh(g.y) * u.y;
    g.z = gelu_tanh(g.z) * u.z;
    g.w = gelu_tanh(g.w) * u.w;
    ((float4*)g_gate)[idx] = g;
}

// ---------------- launch ----------------
static float* symaddr(const void* sym) {
    void* p = nullptr;
    cudaGetSymbolAddress(&p, sym);
    return (float*)p;
}

extern "C" void kernel_launch(void* const* d_in, const int* in_sizes, int n_in,
                              void* d_out, int out_size) {
    const float* hs     = (const float*)d_in[0];
    const float* q_w    = (const float*)d_in[1];
    const float* k_w    = (const float*)d_in[2];
    const float* v_w    = (const float*)d_in[3];
    const float* o_w    = (const float*)d_in[4];
    const float* gate_w = (const float*)d_in[5];
    const float* up_w   = (const float*)d_in[6];
    const float* down_w = (const float*)d_in[7];
    const float* ln1_w  = (const float*)d_in[8];
    const float* ln2_w  = (const float*)d_in[9];
    const int*   amask  = (const int*)d_in[10];
    const int*   pos    = (const int*)d_in[11];
    float* out = (float*)d_out;

    float* xn   = symaddr(g_xn);
    float* q    = symaddr(g_q);
    float* k    = symaddr(g_k);
    float* v    = symaddr(g_v);
    float* attn = symaddr(g_attn);
    float* h1   = symaddr(g_h1);
    float* gate = symaddr(g_gate);
    float* up   = symaddr(g_up);

    // 1) input RMSNorm
    rmsnorm_kernel<<<SQ, 256>>>(hs, ln1_w, xn);

    // 2) QKV projections
    sgemm_kernel<<<dim3(HID / 128, SQ / 128), 256>>>(xn, q_w, nullptr, q, SQ, NH * HD, HID);
    sgemm_kernel<<<dim3((NKV * HD) / 128, SQ / 128), 256>>>(xn, k_w, nullptr, k, SQ, NKV * HD, HID);
    sgemm_kernel<<<dim3((NKV * HD) / 128, SQ / 128), 256>>>(xn, v_w, nullptr, v, SQ, NKV * HD, HID);

    // 3) RoPE in place
    {
        int total = SQ * (NH + NKV) * 128;
        rope_kernel<<<(total + 255) / 256, 256>>>(pos);
    }

    // 4) causal GQA flash attention
    cudaFuncSetAttribute(attn_kernel, cudaFuncAttributeMaxDynamicSharedMemorySize,
                         (int)ATTN_SMEM_BYTES);
    attn_kernel<<<dim3(SQ / 64, NH), 128, ATTN_SMEM_BYTES>>>(amask);

    // 5) O projection + residual
    sgemm_kernel<<<dim3(HID / 128, SQ / 128), 256>>>(attn, o_w, hs, h1, SQ, HID, NH * HD);

    // 6) post-attn RMSNorm
    rmsnorm_kernel<<<SQ, 256>>>(h1, ln2_w, xn);

    // 7) MLP
    sgemm_kernel<<<dim3(FFI / 128, SQ / 128), 256>>>(xn, gate_w, nullptr, gate, SQ, FFI, HID);
    sgemm_kernel<<<dim3(FFI / 128, SQ / 128), 256>>>(xn, up_w, nullptr, up, SQ, FFI, HID);
    {
        size_t n4 = (size_t)SQ * FFI / 4;
        gelumul_kernel<<<(int)((n4 + 255) / 256), 256>>>();
    }
    sgemm_kernel<<<dim3(HID / 128, SQ / 128), 256>>>(gate, down_w, h1, out, SQ, HID, FFI);
}

// round 3
// speedup vs baseline: 1.0029x; 1.0029x over previous
#include <cuda_runtime.h>
#include <cuda_bf16.h>
#include <math.h>

#define SQ 4096
#define HID 2048
#define NH 8
#define NKV 4
#define HD 256
#define FFI 8192

// ---------------- scratch (device globals; no runtime allocation) ----------------
__device__ float g_xn[(size_t)SQ * HID];        // rmsnorm output (reused)
__device__ float g_q[(size_t)SQ * NH * HD];
__device__ float g_k[(size_t)SQ * NKV * HD];
__device__ float g_v[(size_t)SQ * NKV * HD];
__device__ float g_attn[(size_t)SQ * NH * HD];
__device__ float g_h1[(size_t)SQ * HID];        // hidden after attn residual
__device__ float g_gate[(size_t)SQ * FFI];
__device__ float g_up[(size_t)SQ * FFI];

// ---------------- RMSNorm ----------------
__device__ __forceinline__ float warp_red_sum(float v) {
    #pragma unroll
    for (int o = 16; o > 0; o >>= 1) v += __shfl_xor_sync(0xffffffffu, v, o);
    return v;
}

__global__ void rmsnorm_kernel(const float* __restrict__ x, const float* __restrict__ w,
                               float* __restrict__ out) {
    int row = blockIdx.x;
    int tid = threadIdx.x;
    const float* xr = x + (size_t)row * HID;
    float s = 0.f;
    for (int i = tid; i < HID; i += 256) { float v = xr[i]; s += v * v; }
    __shared__ float red[8];
    __shared__ float s_inv;
    s = warp_red_sum(s);
    if ((tid & 31) == 0) red[tid >> 5] = s;
    __syncthreads();
    if (tid == 0) {
        float t = 0.f;
        #pragma unroll
        for (int i = 0; i < 8; i++) t += red[i];
        s_inv = rsqrtf(t / (float)HID + 1e-6f);
    }
    __syncthreads();
    float inv = s_inv;
    float* orow = out + (size_t)row * HID;
    for (int i = tid; i < HID; i += 256) orow[i] = xr[i] * inv * w[i];
}

// ---------------- SGEMM 128x128x8, 8x8 micro-tile, optional residual ----------------
__global__ __launch_bounds__(256) void sgemm_kernel(
    const float* __restrict__ A, const float* __restrict__ B,
    const float* __restrict__ Cres, float* __restrict__ C,
    int M, int N, int K) {
    __shared__ float As[8][128];
    __shared__ float Bs[8][128];
    int bx = blockIdx.x, by = blockIdx.y;
    int tid = threadIdx.x;
    int arow = tid >> 1;            // 0..127
    int acol = (tid & 1) * 4;       // 0 or 4
    int brow = tid >> 5;            // 0..7
    int bcol = (tid & 31) * 4;      // 0..124
    int tx = tid & 15, ty = tid >> 4;
    const float* Ap = A + (size_t)(by * 128) * K;
    const float* Bp = B + (size_t)bx * 128;
    float acc[8][8] = {};
    for (int k0 = 0; k0 < K; k0 += 8) {
        float4 av = *(const float4*)(Ap + (size_t)arow * K + k0 + acol);
        As[acol + 0][arow] = av.x;
        As[acol + 1][arow] = av.y;
        As[acol + 2][arow] = av.z;
        As[acol + 3][arow] = av.w;
        *(float4*)&Bs[brow][bcol] = *(const float4*)(Bp + (size_t)(k0 + brow) * N + bcol);
        __syncthreads();
        #pragma unroll
        for (int k = 0; k < 8; k++) {
            float4 a0 = *(float4*)&As[k][ty * 8];
            float4 a1 = *(float4*)&As[k][ty * 8 + 4];
            float4 b0 = *(float4*)&Bs[k][tx * 8];
            float4 b1 = *(float4*)&Bs[k][tx * 8 + 4];
            float af[8] = {a0.x, a0.y, a0.z, a0.w, a1.x, a1.y, a1.z, a1.w};
            float bf[8] = {b0.x, b0.y, b0.z, b0.w, b1.x, b1.y, b1.z, b1.w};
            #pragma unroll
            for (int i = 0; i < 8; i++)
                #pragma unroll
                for (int j = 0; j < 8; j++) acc[i][j] += af[i] * bf[j];
        }
        __syncthreads();
    }
    #pragma unroll
    for (int i = 0; i < 8; i++) {
        size_t r = (size_t)(by * 128 + ty * 8 + i);
        float* crow = C + r * N + bx * 128 + tx * 8;
        const float* rrow = Cres ? (Cres + r * N + bx * 128 + tx * 8) : nullptr;
        #pragma unroll
        for (int j = 0; j < 8; j += 4) {
            float4 o;
            o.x = acc[i][j + 0]; o.y = acc[i][j + 1];
            o.z = acc[i][j + 2]; o.w = acc[i][j + 3];
            if (rrow) {
                float4 rv = *(const float4*)(rrow + j);
                o.x += rv.x; o.y += rv.y; o.z += rv.z; o.w += rv.w;
            }
            *(float4*)(crow + j) = o;
        }
    }
}

// ---------------- RoPE (in-place on g_q / g_k) ----------------
__global__ void rope_kernel(const int* __restrict__ pos_ids) {
    int idx = blockIdx.x * 256 + threadIdx.x;
    const int total = SQ * (NH + NKV) * 128;
    if (idx >= total) return;
    int j = idx & 127;
    int h = (idx >> 7) % (NH + NKV);
    int s = idx / (128 * (NH + NKV));
    // match reference: inv_freq in fp32, angle = fp32(pos * inv), accurate trig on that angle
    float inv = (float)(1.0 / pow(10000.0, (double)j / 128.0));
    float angf = (float)pos_ids[s] * inv;
    double ang = (double)angf;
    float c = (float)cos(ang);
    float sn = (float)sin(ang);
    float* base = (h < NH) ? (g_q + (size_t)s * (NH * HD) + h * HD)
                           : (g_k + (size_t)s * (NKV * HD) + (h - NH) * HD);
    float x0 = base[j], x1 = base[j + 128];
    base[j]       = x0 * c - x1 * sn;
    base[j + 128] = x1 * c + x0 * sn;
}

// ---------------- Flash attention: 64x64 tiles, online softmax ----------------
// smem: Qs[256][64] (Q^T, pre-scaled), Ks[256][64] (K^T) reused as Vs[64][256],
//       Ss[64][65] (padded), mrow/lrow/srow/mk[64]
#define ATTN_SMEM_FLOATS (256 * 64 + 256 * 64 + 64 * 65 + 4 * 64)
#define ATTN_SMEM_BYTES (ATTN_SMEM_FLOATS * sizeof(float))

__global__ __launch_bounds__(128) void attn_kernel(const int* __restrict__ amask) {
    extern __shared__ float sm[];
    float* Qs = sm;                    // [256][64]
    float* Ks = Qs + 256 * 64;         // [256][64]  (later Vs[64][256])
    float* Ss = Ks + 256 * 64;         // [64][65]
    float* mrow = Ss + 64 * 65;
    float* lrow = mrow + 64;
    float* srow = lrow + 64;
    float* mk = srow + 64;

    const int mt = blockIdx.x;         // query tile
    const int h = blockIdx.y;          // head
    const int m0 = mt * 64;
    const int kvh = h >> 1;            // GQA group of 2
    const int tid = threadIdx.x;
    const int ty = tid >> 3;           // 0..15
    const int tx = tid & 7;            // 0..7

    // load Q^T, pre-scaled by HD^-0.5 = 1/16
    for (int idx = tid; idx < 64 * 64; idx += 128) {
        int i = idx & 63, d4 = idx >> 6;
        float4 qv = *(const float4*)(g_q + (size_t)(m0 + i) * (NH * HD) + h * HD + d4 * 4);
        Qs[(d4 * 4 + 0) * 64 + i] = qv.x * 0.0625f;
        Qs[(d4 * 4 + 1) * 64 + i] = qv.y * 0.0625f;
        Qs[(d4 * 4 + 2) * 64 + i] = qv.z * 0.0625f;
        Qs[(d4 * 4 + 3) * 64 + i] = qv.w * 0.0625f;
    }
    if (tid < 64) { mrow[tid] = -1e30f; lrow[tid] = 0.f; }
    float acc[4][32];
    #pragma unroll
    for (int a = 0; a < 4; a++)
        #pragma unroll
        for (int w = 0; w < 32; w++) acc[a][w] = 0.f;
    __syncthreads();

    for (int jt = 0; jt <= mt; jt++) {
        int n0 = jt * 64;
        // load K^T
        for (int idx = tid; idx < 64 * 64; idx += 128) {
            int c = idx & 63, d4 = idx >> 6;
            float4 kv4 = *(const float4*)(g_k + (size_t)(n0 + c) * (NKV * HD) + kvh * HD + d4 * 4);
            Ks[(d4 * 4 + 0) * 64 + c] = kv4.x;
            Ks[(d4 * 4 + 1) * 64 + c] = kv4.y;
            Ks[(d4 * 4 + 2) * 64 + c] = kv4.z;
            Ks[(d4 * 4 + 3) * 64 + c] = kv4.w;
        }
        if (tid < 64) mk[tid] = (amask[n0 + tid] > 0) ? 0.f : -1e30f;
        __syncthreads();

        // S = Q K^T : each thread rows {ty+16a}, cols {tx*8+b}
        float sreg[4][8];
        #pragma unroll
        for (int a = 0; a < 4; a++)
            #pragma unroll
            for (int b = 0; b < 8; b++) sreg[a][b] = 0.f;
        #pragma unroll 8
        for (int k = 0; k < 256; k++) {
            float a0 = Qs[k * 64 + ty];
            float a1 = Qs[k * 64 + ty + 16];
            float a2 = Qs[k * 64 + ty + 32];
            float a3 = Qs[k * 64 + ty + 48];
            float4 b0 = *(float4*)&Ks[k * 64 + tx * 8];
            float4 b1 = *(float4*)&Ks[k * 64 + tx * 8 + 4];
            float bv[8] = {b0.x, b0.y, b0.z, b0.w, b1.x, b1.y, b1.z, b1.w};
            #pragma unroll
            for (int b = 0; b < 8; b++) {
                sreg[0][b] += a0 * bv[b];
                sreg[1][b] += a1 * bv[b];
                sreg[2][b] += a2 * bv[b];
                sreg[3][b] += a3 * bv[b];
            }
        }
        // mask + store transposed (Ss[c][i], padded row 65)
        #pragma unroll
        for (int a = 0; a < 4; a++)
            #pragma unroll
            for (int b = 0; b < 8; b++) {
                int i = ty + 16 * a, c = tx * 8 + b;
                float v = sreg[a][b] + mk[c];
                if (jt == mt && (n0 + c) > (m0 + i)) v = -1e30f;
                Ss[c * 65 + i] = v;
            }
        __syncthreads();

        // online softmax for row i (threads 0..63); others load V into Ks region
        if (tid < 64) {
            int i = tid;
            float mold = mrow[i];
            float mx = mold;
            #pragma unroll 8
            for (int c = 0; c < 64; c++) mx = fmaxf(mx, Ss[c * 65 + i]);
            float sum = 0.f;
            #pragma unroll 8
            for (int c = 0; c < 64; c++) {
                float p = expf(Ss[c * 65 + i] - mx);
                Ss[c * 65 + i] = p;
                sum += p;
            }
            float sc = expf(mold - mx);
            lrow[i] = lrow[i] * sc + sum;
            mrow[i] = mx;
            srow[i] = sc;
        }
        float* Vs = Ks;  // reuse K buffer as V[c][d]
        for (int idx = tid; idx < 64 * 64; idx += 128) {
            int c = idx >> 6, d4 = idx & 63;
            *(float4*)&Vs[c * 256 + d4 * 4] =
                *(const float4*)(g_v + (size_t)(n0 + c) * (NKV * HD) + kvh * HD + d4 * 4);
        }
        __syncthreads();

        // O = O*scale + P @ V : thread rows {ty+16a}, dims {tx*4 + 32w + 0..3}
        #pragma unroll
        for (int a = 0; a < 4; a++) {
            float scl = srow[ty + 16 * a];
            #pragma unroll
            for (int w = 0; w < 32; w++) acc[a][w] *= scl;
        }
        #pragma unroll 4
        for (int c = 0; c < 64; c++) {
            float p0 = Ss[c * 65 + ty];
            float p1 = Ss[c * 65 + ty + 16];
            float p2 = Ss[c * 65 + ty + 32];
            float p3 = Ss[c * 65 + ty + 48];
            #pragma unroll
            for (int w = 0; w < 8; w++) {
                float4 vv = *(float4*)&Vs[c * 256 + tx * 4 + w * 32];
                acc[0][w * 4 + 0] += p0 * vv.x; acc[0][w * 4 + 1] += p0 * vv.y;
                acc[0][w * 4 + 2] += p0 * vv.z; acc[0][w * 4 + 3] += p0 * vv.w;
                acc[1][w * 4 + 0] += p1 * vv.x; acc[1][w * 4 + 1] += p1 * vv.y;
                acc[1][w * 4 + 2] += p1 * vv.z; acc[1][w * 4 + 3] += p1 * vv.w;
                acc[2][w * 4 + 0] += p2 * vv.x; acc[2][w * 4 + 1] += p2 * vv.y;
                acc[2][w * 4 + 2] += p2 * vv.z; acc[2][w * 4 + 3] += p2 * vv.w;
                acc[3][w * 4 + 0] += p3 * vv.x; acc[3][w * 4 + 1] += p3 * vv.y;
                acc[3][w * 4 + 2] += p3 * vv.z; acc[3][w * 4 + 3] += p3 * vv.w;
            }
        }
        __syncthreads();
    }

    // normalize + write
    #pragma unroll
    for (int a = 0; a < 4; a++) {
        int i = ty + 16 * a;
        float invl = 1.f / lrow[i];
        #pragma unroll
        for (int w = 0; w < 8; w++) {
            float4 o;
            o.x = acc[a][w * 4 + 0] * invl;
            o.y = acc[a][w * 4 + 1] * invl;
            o.z = acc[a][w * 4 + 2] * invl;
            o.w = acc[a][w * 4 + 3] * invl;
            *(float4*)(g_attn + (size_t)(m0 + i) * (NH * HD) + h * HD + tx * 4 + w * 32) = o;
        }
    }
}

// ---------------- gelu(gate) * up, in place into g_gate ----------------
__device__ __forceinline__ float gelu_tanh(float x) {
    float x3 = x * x * x;
    return 0.5f * x * (1.f + tanhf(0.7978845608028654f * (x + 0.044715f * x3)));
}

__global__ void gelumul_kernel() {
    size_t idx = (size_t)blockIdx.x * 256 + threadIdx.x;
    const size_t n4 = (size_t)SQ * FFI / 4;
    if (idx >= n4) return;
    float4 g = ((const float4*)g_gate)[idx];
    float4 u = ((const float4*)g_up)[idx];
    g.x = gelu_tanh(g.x) * u.x;
    g.y = gelu_tanh(g.y) * u.y;
    g.z = gelu_tanh(g.z) * u.z;
    g.w = gelu_tanh(g.w) * u.w;
    ((float4*)g_gate)[idx] = g;
}

// ---------------- launch ----------------
static float* symaddr(const void* sym) {
    void* p = nullptr;
    cudaGetSymbolAddress(&p, sym);
    return (float*)p;
}

extern "C" void kernel_launch(void* const* d_in, const int* in_sizes, int n_in,
                              void* d_out, int out_size) {
    const float* hs     = (const float*)d_in[0];
    const float* q_w    = (const float*)d_in[1];
    const float* k_w    = (const float*)d_in[2];
    const float* v_w    = (const float*)d_in[3];
    const float* o_w    = (const float*)d_in[4];
    const float* gate_w = (const float*)d_in[5];
    const float* up_w   = (const float*)d_in[6];
    const float* down_w = (const float*)d_in[7];
    const float* ln1_w  = (const float*)d_in[8];
    const float* ln2_w  = (const float*)d_in[9];
    const int*   amask  = (const int*)d_in[10];
    const int*   pos    = (const int*)d_in[11];
    float* out = (float*)d_out;

    float* xn   = symaddr(g_xn);
    float* q    = symaddr(g_q);
    float* k    = symaddr(g_k);
    float* v    = symaddr(g_v);
    float* attn = symaddr(g_attn);
    float* h1   = symaddr(g_h1);
    float* gate = symaddr(g_gate);
    float* up   = symaddr(g_up);

    // 1) input RMSNorm
    rmsnorm_kernel<<<SQ, 256>>>(hs, ln1_w, xn);

    // 2) QKV projections
    sgemm_kernel<<<dim3(HID / 128, SQ / 128), 256>>>(xn, q_w, nullptr, q, SQ, NH * HD, HID);
    sgemm_kernel<<<dim3((NKV * HD) / 128, SQ / 128), 256>>>(xn, k_w, nullptr, k, SQ, NKV * HD, HID);
    sgemm_kernel<<<dim3((NKV * HD) / 128, SQ / 128), 256>>>(xn, v_w, nullptr, v, SQ, NKV * HD, HID);

    // 3) RoPE in place
    {
        int total = SQ * (NH + NKV) * 128;
        rope_kernel<<<(total + 255) / 256, 256>>>(pos);
    }

    // 4) causal GQA flash attention
    cudaFuncSetAttribute(attn_kernel, cudaFuncAttributeMaxDynamicSharedMemorySize,
                         (int)ATTN_SMEM_BYTES);
    attn_kernel<<<dim3(SQ / 64, NH), 128, ATTN_SMEM_BYTES>>>(amask);

    // 5) O projection + residual
    sgemm_kernel<<<dim3(HID / 128, SQ / 128), 256>>>(attn, o_w, hs, h1, SQ, HID, NH * HD);

    // 6) post-attn RMSNorm
    rmsnorm_kernel<<<SQ, 256>>>(h1, ln2_w, xn);

    // 7) MLP
    sgemm_kernel<<<dim3(FFI / 128, SQ / 128), 256>>>(xn, gate_w, nullptr, gate, SQ, FFI, HID);
    sgemm_kernel<<<dim3(FFI / 128, SQ / 128), 256>>>(xn, up_w, nullptr, up, SQ, FFI, HID);
    {
        size_t n4 = (size_t)SQ * FFI / 4;
        gelumul_kernel<<<(int)((n4 + 255) / 256), 256>>>();
    }
    sgemm_kernel<<<dim3(HID / 128, SQ / 128), 256>>>(gate, down_w, h1, out, SQ, HID, FFI);
}

// round 5
// speedup vs baseline: 1.9735x; 1.9678x over previous
#include <cuda_runtime.h>
#include <cuda_bf16.h>
#include <math.h>
#include <stdint.h>

#define SQ 4096
#define HID 2048
#define NH 8
#define NKV 4
#define HD 256
#define FFI 8192

typedef __nv_bfloat16 bf;

// ================= device scratch =================
__device__ bf g_xn_h[(size_t)SQ * HID];
__device__ bf g_xn_l[(size_t)SQ * HID];
__device__ float g_q[(size_t)SQ * NH * HD];
__device__ float g_k[(size_t)SQ * NKV * HD];
__device__ float g_v[(size_t)SQ * NKV * HD];
__device__ bf g_attn_h[(size_t)SQ * HID];
__device__ bf g_attn_l[(size_t)SQ * HID];
__device__ float g_h1[(size_t)SQ * HID];
__device__ float g_gate[(size_t)SQ * FFI];
__device__ float g_up[(size_t)SQ * FFI];
__device__ bf g_gact_h[(size_t)SQ * FFI];
__device__ bf g_gact_l[(size_t)SQ * FFI];
// transposed split weights, layout [N, K]
__device__ bf g_qw_h[(size_t)HID * HID], g_qw_l[(size_t)HID * HID];
__device__ bf g_kw_h[(size_t)(NKV * HD) * HID], g_kw_l[(size_t)(NKV * HD) * HID];
__device__ bf g_vw_h[(size_t)(NKV * HD) * HID], g_vw_l[(size_t)(NKV * HD) * HID];
__device__ bf g_ow_h[(size_t)HID * HID], g_ow_l[(size_t)HID * HID];
__device__ bf g_gw_h[(size_t)FFI * HID], g_gw_l[(size_t)FFI * HID];
__device__ bf g_uw_h[(size_t)FFI * HID], g_uw_l[(size_t)FFI * HID];
__device__ bf g_dw_h[(size_t)HID * FFI], g_dw_l[(size_t)HID * FFI];

// ================= PTX helpers (base-target only: cp.async / ldmatrix / mma.sync) =================
__device__ __forceinline__ uint32_t smem_u32(const void* p) {
    return (uint32_t)__cvta_generic_to_shared(p);
}
__device__ __forceinline__ void cpasync16(uint32_t s, const void* g) {
    asm volatile("cp.async.cg.shared.global [%0], [%1], 16;" :: "r"(s), "l"(g));
}
__device__ __forceinline__ void cp_commit() { asm volatile("cp.async.commit_group;" ::: "memory"); }
template <int N> __device__ __forceinline__ void cp_wait() {
    asm volatile("cp.async.wait_group %0;" :: "n"(N) : "memory");
}
__device__ __forceinline__ void ldsm4(uint32_t* r, uint32_t a) {
    asm volatile("ldmatrix.sync.aligned.m8n8.x4.shared.b16 {%0,%1,%2,%3}, [%4];"
                 : "=r"(r[0]), "=r"(r[1]), "=r"(r[2]), "=r"(r[3]) : "r"(a));
}
__device__ __forceinline__ void ldsm2(uint32_t* r, uint32_t a) {
    asm volatile("ldmatrix.sync.aligned.m8n8.x2.shared.b16 {%0,%1}, [%2];"
                 : "=r"(r[0]), "=r"(r[1]) : "r"(a));
}
__device__ __forceinline__ void mma16816(float* d, const uint32_t* a, const uint32_t* b) {
    asm volatile(
        "mma.sync.aligned.m16n8k16.row.col.f32.bf16.bf16.f32 "
        "{%0,%1,%2,%3}, {%4,%5,%6,%7}, {%8,%9}, {%0,%1,%2,%3};"
        : "+f"(d[0]), "+f"(d[1]), "+f"(d[2]), "+f"(d[3])
        : "r"(a[0]), "r"(a[1]), "r"(a[2]), "r"(a[3]), "r"(b[0]), "r"(b[1]));
}
__device__ __forceinline__ void split2(float v, bf& h, bf& l) {
    h = __float2bfloat16(v);
    l = __float2bfloat16(v - __bfloat162float(h));
}

// ================= HMMA split-bf16 GEMM =================
// C[M,N] = (Ah+Al)[M,K] @ (Bh+Bl)^T, B given as [N,K]. Tile 128x128, Kc=32.
// Smem stage layout (padded rows: 32+8 bf16 = 80B stride):
//   Ah @ 0, Al @ 10240, Bh @ 20480, Bl @ 30720;  stage stride 40960, 3 stages.
#define KC 32
#define ROWB 80           /* bytes per padded smem row */
#define SPLIT_OFF 10240
#define B_OFF 20480
#define STAGE_BYTES 40960
#define GEMM_SMEM (3 * STAGE_BYTES)

__device__ __forceinline__ void gemm_load_chunk(
    uint32_t st, int tid,
    const bf* gAh, const bf* gAl, const bf* gBh, const bf* gBl, int k0, int K)
{
    #pragma unroll
    for (int rep = 0; rep < 2; rep++) {
        int id = tid + rep * 256;       // 0..511
        int r = id >> 2;                // 0..127
        int g = id & 3;                 // 16B group within 64B row
        size_t go = (size_t)r * K + k0 + g * 8;
        uint32_t so = st + (uint32_t)(r * ROWB + g * 16);
        cpasync16(so,                  gAh + go);
        cpasync16(so + SPLIT_OFF,      gAl + go);
        cpasync16(so + B_OFF,          gBh + go);
        cpasync16(so + B_OFF + SPLIT_OFF, gBl + go);
    }
    cp_commit();
}

__global__ __launch_bounds__(256) void mma_gemm_kernel(
    const bf* __restrict__ Ah, const bf* __restrict__ Al,
    const bf* __restrict__ Bh, const bf* __restrict__ Bl,
    const float* __restrict__ Cres, float* __restrict__ C, int N, int K)
{
    extern __shared__ __align__(128) char smem[];
    const uint32_t sb = smem_u32(smem);
    const int tid = threadIdx.x;
    const int lane = tid & 31;
    const int wid = tid >> 5;
    const int wm = wid >> 2;            // 0..1 : 64-row slice
    const int wn = wid & 3;             // 0..3 : 32-col slice
    const int m0 = blockIdx.x * 128;
    const int n0 = blockIdx.y * 128;

    const bf* gAh = Ah + (size_t)m0 * K;
    const bf* gAl = Al + (size_t)m0 * K;
    const bf* gBh = Bh + (size_t)n0 * K;
    const bf* gBl = Bl + (size_t)n0 * K;
    const int nch = K / KC;

    float acc[4][4][4];
    #pragma unroll
    for (int mt = 0; mt < 4; mt++)
        #pragma unroll
        for (int nt = 0; nt < 4; nt++)
            #pragma unroll
            for (int e = 0; e < 4; e++) acc[mt][nt][e] = 0.f;

    // prologue: fill 3 stages
    #pragma unroll
    for (int c = 0; c < 3; c++)
        gemm_load_chunk(sb + c * STAGE_BYTES, tid, gAh, gAl, gBh, gBl, c * KC, K);

    // per-lane ldmatrix base offsets (within a stage)
    const uint32_t aOff = (uint32_t)((wm * 64 + (lane & 15)) * ROWB + ((lane >> 4) * 8) * 2);
    const uint32_t bOff = (uint32_t)(B_OFF + (wn * 32 + (lane & 7)) * ROWB + (((lane >> 3) & 1) * 8) * 2);

    for (int i = 0; i < nch; i++) {
        cp_wait<2>();
        __syncthreads();
        uint32_t st = sb + (uint32_t)((i % 3) * STAGE_BYTES);
        uint32_t aB = st + aOff;
        uint32_t bB = st + bOff;
        #pragma unroll
        for (int ks = 0; ks < 2; ks++) {
            uint32_t ak = aB + ks * 32;   // +16 cols * 2B
            uint32_t bk = bB + ks * 32;
            uint32_t ah[4][4], al[4][4], bh[4][2], bl[4][2];
            #pragma unroll
            for (int mt = 0; mt < 4; mt++) {
                ldsm4(ah[mt], ak + mt * (16 * ROWB));
                ldsm4(al[mt], ak + SPLIT_OFF + mt * (16 * ROWB));
            }
            #pragma unroll
            for (int nt = 0; nt < 4; nt++) {
                ldsm2(bh[nt], bk + nt * (8 * ROWB));
                ldsm2(bl[nt], bk + SPLIT_OFF + nt * (8 * ROWB));
            }
            #pragma unroll
            for (int mt = 0; mt < 4; mt++)
                #pragma unroll
                for (int nt = 0; nt < 4; nt++) {
                    mma16816(acc[mt][nt], ah[mt], bh[nt]);
                    mma16816(acc[mt][nt], ah[mt], bl[nt]);
                    mma16816(acc[mt][nt], al[mt], bh[nt]);
                }
        }
        __syncthreads();
        if (i + 3 < nch)
            gemm_load_chunk(st, tid, gAh, gAl, gBh, gBl, (i + 3) * KC, K);
        else
            cp_commit();   // keep group count in lockstep
    }

    // epilogue: d0,d1 -> (row, col..col+1); d2,d3 -> (row+8)
    const int rbase = m0 + wm * 64 + (lane >> 2);
    const int cbase = n0 + wn * 32 + (lane & 3) * 2;
    #pragma unroll
    for (int mt = 0; mt < 4; mt++) {
        #pragma unroll
        for (int nt = 0; nt < 4; nt++) {
            int r = rbase + mt * 16;
            int c = cbase + nt * 8;
            float* p0 = C + (size_t)r * N + c;
            float* p1 = C + (size_t)(r + 8) * N + c;
            float2 v0 = make_float2(acc[mt][nt][0], acc[mt][nt][1]);
            float2 v1 = make_float2(acc[mt][nt][2], acc[mt][nt][3]);
            if (Cres) {
                const float2 r0 = *(const float2*)(Cres + (size_t)r * N + c);
                const float2 r1 = *(const float2*)(Cres + (size_t)(r + 8) * N + c);
                v0.x += r0.x; v0.y += r0.y;
                v1.x += r1.x; v1.y += r1.y;
            }
            *(float2*)p0 = v0;
            *(float2*)p1 = v1;
        }
    }
}

// ================= weight transpose+split: W[K,N] -> T[N,K] bf16 hi/lo =================
__global__ __launch_bounds__(256) void wsplit_kernel(
    const float* __restrict__ W, bf* __restrict__ Th, bf* __restrict__ Tl, int K, int N)
{
    __shared__ float t[32][33];
    int n0 = blockIdx.x * 32, k0 = blockIdx.y * 32;
    int tid = threadIdx.x;
    int tn = tid & 31, tk = tid >> 5;
    #pragma unroll
    for (int i = 0; i < 4; i++)
        t[tk + 8 * i][tn] = W[(size_t)(k0 + tk + 8 * i) * N + n0 + tn];
    __syncthreads();
    #pragma unroll
    for (int i = 0; i < 4; i++) {
        int r = tk + 8 * i, c = tn;
        float v = t[c][r];
        bf h, l;
        split2(v, h, l);
        size_t o = (size_t)(n0 + r) * K + k0 + c;
        Th[o] = h;
        Tl[o] = l;
    }
}

// ================= RMSNorm -> bf16 hi/lo =================
__device__ __forceinline__ float warp_red_sum(float v) {
    #pragma unroll
    for (int o = 16; o > 0; o >>= 1) v += __shfl_xor_sync(0xffffffffu, v, o);
    return v;
}

__global__ void rmsnorm_split_kernel(const float* __restrict__ x, const float* __restrict__ w,
                                     bf* __restrict__ oh, bf* __restrict__ ol) {
    int row = blockIdx.x;
    int tid = threadIdx.x;
    const float* xr = x + (size_t)row * HID;
    float s = 0.f;
    for (int i = tid; i < HID; i += 256) { float v = xr[i]; s += v * v; }
    __shared__ float red[8];
    __shared__ float s_inv;
    s = warp_red_sum(s);
    if ((tid & 31) == 0) red[tid >> 5] = s;
    __syncthreads();
    if (tid == 0) {
        float t = 0.f;
        #pragma unroll
        for (int i = 0; i < 8; i++) t += red[i];
        s_inv = rsqrtf(t / (float)HID + 1e-6f);
    }
    __syncthreads();
    float inv = s_inv;
    bf* hrow = oh + (size_t)row * HID;
    bf* lrow = ol + (size_t)row * HID;
    for (int i = tid * 2; i < HID; i += 512) {
        float v0 = xr[i] * inv * w[i];
        float v1 = xr[i + 1] * inv * w[i + 1];
        bf h0, l0, h1, l1;
        split2(v0, h0, l0);
        split2(v1, h1, l1);
        *(__nv_bfloat162*)(hrow + i) = __halves2bfloat162(h0, h1);
        *(__nv_bfloat162*)(lrow + i) = __halves2bfloat162(l0, l1);
    }
}

// ================= RoPE: one thread per (s,j), all 12 heads =================
__global__ void rope_kernel(const int* __restrict__ pos_ids) {
    int idx = blockIdx.x * 256 + threadIdx.x;
    if (idx >= SQ * 128) return;
    int j = idx & 127;
    int s = idx >> 7;
    float inv = (float)(1.0 / pow(10000.0, (double)j / 128.0));
    float angf = (float)pos_ids[s] * inv;
    double ang = (double)angf;
    float c = (float)cos(ang);
    float sn = (float)sin(ang);
    #pragma unroll
    for (int h = 0; h < NH; h++) {
        float* b = g_q + (size_t)s * (NH * HD) + h * HD;
        float x0 = b[j], x1 = b[j + 128];
        b[j]       = x0 * c - x1 * sn;
        b[j + 128] = x1 * c + x0 * sn;
    }
    #pragma unroll
    for (int h = 0; h < NKV; h++) {
        float* b = g_k + (size_t)s * (NKV * HD) + h * HD;
        float x0 = b[j], x1 = b[j + 128];
        b[j]       = x0 * c - x1 * sn;
        b[j + 128] = x1 * c + x0 * sn;
    }
}

// ================= Flash attention (fp32), epilogue emits bf16 hi/lo =================
#define ATTN_SMEM_FLOATS (256 * 64 + 256 * 64 + 64 * 65 + 4 * 64)
#define ATTN_SMEM_BYTES (ATTN_SMEM_FLOATS * sizeof(float))

__global__ __launch_bounds__(128) void attn_kernel(const int* __restrict__ amask) {
    extern __shared__ float sm[];
    float* Qs = sm;
    float* Ks = Qs + 256 * 64;
    float* Ss = Ks + 256 * 64;
    float* mrow = Ss + 64 * 65;
    float* lrow = mrow + 64;
    float* srow = lrow + 64;
    float* mk = srow + 64;

    const int mt = blockIdx.x;
    const int h = blockIdx.y;
    const int m0 = mt * 64;
    const int kvh = h >> 1;
    const int tid = threadIdx.x;
    const int ty = tid >> 3;
    const int tx = tid & 7;

    for (int idx = tid; idx < 64 * 64; idx += 128) {
        int i = idx & 63, d4 = idx >> 6;
        float4 qv = *(const float4*)(g_q + (size_t)(m0 + i) * (NH * HD) + h * HD + d4 * 4);
        Qs[(d4 * 4 + 0) * 64 + i] = qv.x * 0.0625f;
        Qs[(d4 * 4 + 1) * 64 + i] = qv.y * 0.0625f;
        Qs[(d4 * 4 + 2) * 64 + i] = qv.z * 0.0625f;
        Qs[(d4 * 4 + 3) * 64 + i] = qv.w * 0.0625f;
    }
    if (tid < 64) { mrow[tid] = -1e30f; lrow[tid] = 0.f; }
    float acc[4][32];
    #pragma unroll
    for (int a = 0; a < 4; a++)
        #pragma unroll
        for (int w = 0; w < 32; w++) acc[a][w] = 0.f;
    __syncthreads();

    for (int jt = 0; jt <= mt; jt++) {
        int n0 = jt * 64;
        for (int idx = tid; idx < 64 * 64; idx += 128) {
            int c = idx & 63, d4 = idx >> 6;
            float4 kv4 = *(const float4*)(g_k + (size_t)(n0 + c) * (NKV * HD) + kvh * HD + d4 * 4);
            Ks[(d4 * 4 + 0) * 64 + c] = kv4.x;
            Ks[(d4 * 4 + 1) * 64 + c] = kv4.y;
            Ks[(d4 * 4 + 2) * 64 + c] = kv4.z;
            Ks[(d4 * 4 + 3) * 64 + c] = kv4.w;
        }
        if (tid < 64) mk[tid] = (amask[n0 + tid] > 0) ? 0.f : -1e30f;
        __syncthreads();

        float sreg[4][8];
        #pragma unroll
        for (int a = 0; a < 4; a++)
            #pragma unroll
            for (int b = 0; b < 8; b++) sreg[a][b] = 0.f;
        #pragma unroll 8
        for (int k = 0; k < 256; k++) {
            float a0 = Qs[k * 64 + ty];
            float a1 = Qs[k * 64 + ty + 16];
            float a2 = Qs[k * 64 + ty + 32];
            float a3 = Qs[k * 64 + ty + 48];
            float4 b0 = *(float4*)&Ks[k * 64 + tx * 8];
            float4 b1 = *(float4*)&Ks[k * 64 + tx * 8 + 4];
            float bv[8] = {b0.x, b0.y, b0.z, b0.w, b1.x, b1.y, b1.z, b1.w};
            #pragma unroll
            for (int b = 0; b < 8; b++) {
                sreg[0][b] += a0 * bv[b];
                sreg[1][b] += a1 * bv[b];
                sreg[2][b] += a2 * bv[b];
                sreg[3][b] += a3 * bv[b];
            }
        }
        #pragma unroll
        for (int a = 0; a < 4; a++)
            #pragma unroll
            for (int b = 0; b < 8; b++) {
                int i = ty + 16 * a, c = tx * 8 + b;
                float v = sreg[a][b] + mk[c];
                if (jt == mt && (n0 + c) > (m0 + i)) v = -1e30f;
                Ss[c * 65 + i] = v;
            }
        __syncthreads();

        if (tid < 64) {
            int i = tid;
            float mold = mrow[i];
            float mx = mold;
            #pragma unroll 8
            for (int c = 0; c < 64; c++) mx = fmaxf(mx, Ss[c * 65 + i]);
            float sum = 0.f;
            #pragma unroll 8
            for (int c = 0; c < 64; c++) {
                float p = expf(Ss[c * 65 + i] - mx);
                Ss[c * 65 + i] = p;
                sum += p;
            }
            float sc = expf(mold - mx);
            lrow[i] = lrow[i] * sc + sum;
            mrow[i] = mx;
            srow[i] = sc;
        }
        float* Vs = Ks;
        for (int idx = tid; idx < 64 * 64; idx += 128) {
            int c = idx >> 6, d4 = idx & 63;
            *(float4*)&Vs[c * 256 + d4 * 4] =
                *(const float4*)(g_v + (size_t)(n0 + c) * (NKV * HD) + kvh * HD + d4 * 4);
        }
        __syncthreads();

        #pragma unroll
        for (int a = 0; a < 4; a++) {
            float scl = srow[ty + 16 * a];
            #pragma unroll
            for (int w = 0; w < 32; w++) acc[a][w] *= scl;
        }
        #pragma unroll 4
        for (int c = 0; c < 64; c++) {
            float p0 = Ss[c * 65 + ty];
            float p1 = Ss[c * 65 + ty + 16];
            float p2 = Ss[c * 65 + ty + 32];
            float p3 = Ss[c * 65 + ty + 48];
            #pragma unroll
            for (int w = 0; w < 8; w++) {
                float4 vv = *(float4*)&Vs[c * 256 + tx * 4 + w * 32];
                acc[0][w * 4 + 0] += p0 * vv.x; acc[0][w * 4 + 1] += p0 * vv.y;
                acc[0][w * 4 + 2] += p0 * vv.z; acc[0][w * 4 + 3] += p0 * vv.w;
                acc[1][w * 4 + 0] += p1 * vv.x; acc[1][w * 4 + 1] += p1 * vv.y;
                acc[1][w * 4 + 2] += p1 * vv.z; acc[1][w * 4 + 3] += p1 * vv.w;
                acc[2][w * 4 + 0] += p2 * vv.x; acc[2][w * 4 + 1] += p2 * vv.y;
                acc[2][w * 4 + 2] += p2 * vv.z; acc[2][w * 4 + 3] += p2 * vv.w;
                acc[3][w * 4 + 0] += p3 * vv.x; acc[3][w * 4 + 1] += p3 * vv.y;
                acc[3][w * 4 + 2] += p3 * vv.z; acc[3][w * 4 + 3] += p3 * vv.w;
            }
        }
        __syncthreads();
    }

    #pragma unroll
    for (int a = 0; a < 4; a++) {
        int i = ty + 16 * a;
        float invl = 1.f / lrow[i];
        #pragma unroll
        for (int w = 0; w < 8; w++) {
            float o0 = acc[a][w * 4 + 0] * invl;
            float o1 = acc[a][w * 4 + 1] * invl;
            float o2 = acc[a][w * 4 + 2] * invl;
            float o3 = acc[a][w * 4 + 3] * invl;
            bf h0, l0, h1, l1, h2, l2, h3, l3;
            split2(o0, h0, l0); split2(o1, h1, l1);
            split2(o2, h2, l2); split2(o3, h3, l3);
            size_t off = (size_t)(m0 + i) * (NH * HD) + h * HD + tx * 4 + w * 32;
            *(__nv_bfloat162*)(g_attn_h + off)     = __halves2bfloat162(h0, h1);
            *(__nv_bfloat162*)(g_attn_h + off + 2) = __halves2bfloat162(h2, h3);
            *(__nv_bfloat162*)(g_attn_l + off)     = __halves2bfloat162(l0, l1);
            *(__nv_bfloat162*)(g_attn_l + off + 2) = __halves2bfloat162(l2, l3);
        }
    }
}

// ================= gelu(gate)*up -> bf16 hi/lo =================
__device__ __forceinline__ float gelu_tanh(float x) {
    float x3 = x * x * x;
    return 0.5f * x * (1.f + tanhf(0.7978845608028654f * (x + 0.044715f * x3)));
}

__global__ void gelumul_split_kernel() {
    size_t idx = (size_t)blockIdx.x * 256 + threadIdx.x;
    const size_t n4 = (size_t)SQ * FFI / 4;
    if (idx >= n4) return;
    float4 g = ((const float4*)g_gate)[idx];
    float4 u = ((const float4*)g_up)[idx];
    float m0 = gelu_tanh(g.x) * u.x;
    float m1 = gelu_tanh(g.y) * u.y;
    float m2 = gelu_tanh(g.z) * u.z;
    float m3 = gelu_tanh(g.w) * u.w;
    bf h0, l0, h1, l1, h2, l2, h3, l3;
    split2(m0, h0, l0); split2(m1, h1, l1);
    split2(m2, h2, l2); split2(m3, h3, l3);
    ((__nv_bfloat162*)g_gact_h)[idx * 2]     = __halves2bfloat162(h0, h1);
    ((__nv_bfloat162*)g_gact_h)[idx * 2 + 1] = __halves2bfloat162(h2, h3);
    ((__nv_bfloat162*)g_gact_l)[idx * 2]     = __halves2bfloat162(l0, l1);
    ((__nv_bfloat162*)g_gact_l)[idx * 2 + 1] = __halves2bfloat162(l2, l3);
}

// ================= launch =================
template <typename T>
static T* symaddr(const void* sym) {
    void* p = nullptr;
    cudaGetSymbolAddress(&p, sym);
    return (T*)p;
}

extern "C" void kernel_launch(void* const* d_in, const int* in_sizes, int n_in,
                              void* d_out, int out_size) {
    (void)in_sizes; (void)n_in; (void)out_size;
    const float* hs     = (const float*)d_in[0];
    const float* q_w    = (const float*)d_in[1];
    const float* k_w    = (const float*)d_in[2];
    const float* v_w    = (const float*)d_in[3];
    const float* o_w    = (const float*)d_in[4];
    const float* gate_w = (const float*)d_in[5];
    const float* up_w   = (const float*)d_in[6];
    const float* down_w = (const float*)d_in[7];
    const float* ln1_w  = (const float*)d_in[8];
    const float* ln2_w  = (const float*)d_in[9];
    const int*   amask  = (const int*)d_in[10];
    const int*   pos    = (const int*)d_in[11];
    float* out = (float*)d_out;

    bf* xn_h = symaddr<bf>(g_xn_h);   bf* xn_l = symaddr<bf>(g_xn_l);
    float* q = symaddr<float>(g_q);
    float* k = symaddr<float>(g_k);
    float* v = symaddr<float>(g_v);
    bf* at_h = symaddr<bf>(g_attn_h); bf* at_l = symaddr<bf>(g_attn_l);
    float* h1 = symaddr<float>(g_h1);
    float* gate = symaddr<float>(g_gate);
    float* up = symaddr<float>(g_up);
    bf* ga_h = symaddr<bf>(g_gact_h); bf* ga_l = symaddr<bf>(g_gact_l);
    bf* qwh = symaddr<bf>(g_qw_h); bf* qwl = symaddr<bf>(g_qw_l);
    bf* kwh = symaddr<bf>(g_kw_h); bf* kwl = symaddr<bf>(g_kw_l);
    bf* vwh = symaddr<bf>(g_vw_h); bf* vwl = symaddr<bf>(g_vw_l);
    bf* owh = symaddr<bf>(g_ow_h); bf* owl = symaddr<bf>(g_ow_l);
    bf* gwh = symaddr<bf>(g_gw_h); bf* gwl = symaddr<bf>(g_gw_l);
    bf* uwh = symaddr<bf>(g_uw_h); bf* uwl = symaddr<bf>(g_uw_l);
    bf* dwh = symaddr<bf>(g_dw_h); bf* dwl = symaddr<bf>(g_dw_l);

    cudaFuncSetAttribute(mma_gemm_kernel, cudaFuncAttributeMaxDynamicSharedMemorySize, GEMM_SMEM);
    cudaFuncSetAttribute(attn_kernel, cudaFuncAttributeMaxDynamicSharedMemorySize,
                         (int)ATTN_SMEM_BYTES);

    // 0) weight transpose + split
    wsplit_kernel<<<dim3(HID / 32, HID / 32), 256>>>(q_w, qwh, qwl, HID, HID);
    wsplit_kernel<<<dim3((NKV * HD) / 32, HID / 32), 256>>>(k_w, kwh, kwl, HID, NKV * HD);
    wsplit_kernel<<<dim3((NKV * HD) / 32, HID / 32), 256>>>(v_w, vwh, vwl, HID, NKV * HD);
    wsplit_kernel<<<dim3(HID / 32, HID / 32), 256>>>(o_w, owh, owl, HID, HID);
    wsplit_kernel<<<dim3(FFI / 32, HID / 32), 256>>>(gate_w, gwh, gwl, HID, FFI);
    wsplit_kernel<<<dim3(FFI / 32, HID / 32), 256>>>(up_w, uwh, uwl, HID, FFI);
    wsplit_kernel<<<dim3(HID / 32, FFI / 32), 256>>>(down_w, dwh, dwl, FFI, HID);

    // 1) input RMSNorm (split)
    rmsnorm_split_kernel<<<SQ, 256>>>(hs, ln1_w, xn_h, xn_l);

    // 2) QKV projections (HMMA)
    mma_gemm_kernel<<<dim3(SQ / 128, HID / 128), 256, GEMM_SMEM>>>(
        xn_h, xn_l, qwh, qwl, nullptr, q, HID, HID);
    mma_gemm_kernel<<<dim3(SQ / 128, (NKV * HD) / 128), 256, GEMM_SMEM>>>(
        xn_h, xn_l, kwh, kwl, nullptr, k, NKV * HD, HID);
    mma_gemm_kernel<<<dim3(SQ / 128, (NKV * HD) / 128), 256, GEMM_SMEM>>>(
        xn_h, xn_l, vwh, vwl, nullptr, v, NKV * HD, HID);

    // 3) RoPE
    rope_kernel<<<(SQ * 128 + 255) / 256, 256>>>(pos);

    // 4) flash attention (fp32), outputs split
    attn_kernel<<<dim3(SQ / 64, NH), 128, ATTN_SMEM_BYTES>>>(amask);

    // 5) O projection + residual
    mma_gemm_kernel<<<dim3(SQ / 128, HID / 128), 256, GEMM_SMEM>>>(
        at_h, at_l, owh, owl, hs, h1, HID, HID);

    // 6) post-attn RMSNorm (split)
    rmsnorm_split_kernel<<<SQ, 256>>>(h1, ln2_w, xn_h, xn_l);

    // 7) MLP
    mma_gemm_kernel<<<dim3(SQ / 128, FFI / 128), 256, GEMM_SMEM>>>(
        xn_h, xn_l, gwh, gwl, nullptr, gate, FFI, HID);
    mma_gemm_kernel<<<dim3(SQ / 128, FFI / 128), 256, GEMM_SMEM>>>(
        xn_h, xn_l, uwh, uwl, nullptr, up, FFI, HID);
    {
        size_t n4 = (size_t)SQ * FFI / 4;
        gelumul_split_kernel<<<(int)((n4 + 255) / 256), 256>>>();
    }
    mma_gemm_kernel<<<dim3(SQ / 128, HID / 128), 256, GEMM_SMEM>>>(
        ga_h, ga_l, dwh, dwl, h1, out, HID, FFI);
}

// round 6
// speedup vs baseline: 3.0281x; 1.5344x over previous
#include <cuda_runtime.h>
#include <cuda_bf16.h>
#include <cuda_fp16.h>
#include <math.h>
#include <stdint.h>

#define SQ 4096
#define HID 2048
#define NH 8
#define NKV 4
#define HD 256
#define FFI 8192

// ================= device scratch =================
__device__ __half g_xn[(size_t)SQ * HID];         // rmsnorm output, fp16
__device__ float g_q[(size_t)SQ * NH * HD];
__device__ float g_k[(size_t)SQ * NKV * HD];
__device__ float g_v[(size_t)SQ * NKV * HD];
__device__ __half g_attn[(size_t)SQ * HID];       // attention output, fp16
__device__ float g_h1[(size_t)SQ * HID];
__device__ float g_gate[(size_t)SQ * FFI];
__device__ float g_up[(size_t)SQ * FFI];
__device__ __half g_gact[(size_t)SQ * FFI];       // gelu(gate)*up, fp16
// transposed fp16 weights, layout [N, K]
__device__ __half g_qw[(size_t)HID * HID];
__device__ __half g_kw[(size_t)(NKV * HD) * HID];
__device__ __half g_vw[(size_t)(NKV * HD) * HID];
__device__ __half g_ow[(size_t)HID * HID];
__device__ __half g_gw[(size_t)FFI * HID];
__device__ __half g_uw[(size_t)FFI * HID];
__device__ __half g_dw[(size_t)HID * FFI];

// ================= PTX helpers (base-target: cp.async / ldmatrix / mma.sync) =================
__device__ __forceinline__ uint32_t smem_u32(const void* p) {
    return (uint32_t)__cvta_generic_to_shared(p);
}
__device__ __forceinline__ void cpasync16(uint32_t s, const void* g) {
    asm volatile("cp.async.cg.shared.global [%0], [%1], 16;" :: "r"(s), "l"(g));
}
__device__ __forceinline__ void cp_commit() { asm volatile("cp.async.commit_group;" ::: "memory"); }
template <int N> __device__ __forceinline__ void cp_wait() {
    asm volatile("cp.async.wait_group %0;" :: "n"(N) : "memory");
}
__device__ __forceinline__ void ldsm4(uint32_t* r, uint32_t a) {
    asm volatile("ldmatrix.sync.aligned.m8n8.x4.shared.b16 {%0,%1,%2,%3}, [%4];"
                 : "=r"(r[0]), "=r"(r[1]), "=r"(r[2]), "=r"(r[3]) : "r"(a));
}
__device__ __forceinline__ void ldsm2(uint32_t* r, uint32_t a) {
    asm volatile("ldmatrix.sync.aligned.m8n8.x2.shared.b16 {%0,%1}, [%2];"
                 : "=r"(r[0]), "=r"(r[1]) : "r"(a));
}
__device__ __forceinline__ void mma16816(float* d, const uint32_t* a, const uint32_t* b) {
    asm volatile(
        "mma.sync.aligned.m16n8k16.row.col.f32.f16.f16.f32 "
        "{%0,%1,%2,%3}, {%4,%5,%6,%7}, {%8,%9}, {%0,%1,%2,%3};"
        : "+f"(d[0]), "+f"(d[1]), "+f"(d[2]), "+f"(d[3])
        : "r"(a[0]), "r"(a[1]), "r"(a[2]), "r"(a[3]), "r"(b[0]), "r"(b[1]));
}

// ================= fp16 HMMA GEMM =================
// C[M,N] = A[M,K](fp16) @ B[N,K](fp16)^T. Tile 128x128, Kc=32, 4-stage cp.async.
// Smem per stage: A @0 (128 rows x 80B padded), B @10240; stage stride 20480.
#define KC 32
#define ROWB 80
#define B_OFF 10240
#define STAGE_BYTES 20480
#define NSTAGE 4
#define GEMM_SMEM (NSTAGE * STAGE_BYTES)

__device__ __forceinline__ void gemm_load_chunk(
    uint32_t st, int tid, const __half* gA, const __half* gB, int k0, int K)
{
    #pragma unroll
    for (int rep = 0; rep < 2; rep++) {
        int id = tid + rep * 256;       // 0..511
        int r = id >> 2;                // 0..127
        int g = id & 3;                 // 16B group within 64B row
        size_t go = (size_t)r * K + k0 + g * 8;
        uint32_t so = st + (uint32_t)(r * ROWB + g * 16);
        cpasync16(so,         gA + go);
        cpasync16(so + B_OFF, gB + go);
    }
    cp_commit();
}

__global__ __launch_bounds__(256) void mma_gemm_kernel(
    const __half* __restrict__ A, const __half* __restrict__ B,
    const float* __restrict__ Cres, float* __restrict__ C, int N, int K)
{
    extern __shared__ __align__(128) char smem[];
    const uint32_t sb = smem_u32(smem);
    const int tid = threadIdx.x;
    const int lane = tid & 31;
    const int wid = tid >> 5;
    const int wm = wid >> 2;            // 0..1
    const int wn = wid & 3;             // 0..3
    const int m0 = blockIdx.x * 128;
    const int n0 = blockIdx.y * 128;

    const __half* gA = A + (size_t)m0 * K;
    const __half* gB = B + (size_t)n0 * K;
    const int nch = K / KC;

    float acc[4][4][4];
    #pragma unroll
    for (int mt = 0; mt < 4; mt++)
        #pragma unroll
        for (int nt = 0; nt < 4; nt++)
            #pragma unroll
            for (int e = 0; e < 4; e++) acc[mt][nt][e] = 0.f;

    #pragma unroll
    for (int c = 0; c < NSTAGE; c++)
        gemm_load_chunk(sb + c * STAGE_BYTES, tid, gA, gB, c * KC, K);

    const uint32_t aOff = (uint32_t)((wm * 64 + (lane & 15)) * ROWB + ((lane >> 4) * 8) * 2);
    const uint32_t bOff = (uint32_t)(B_OFF + (wn * 32 + (lane & 7)) * ROWB + (((lane >> 3) & 1) * 8) * 2);

    for (int i = 0; i < nch; i++) {
        cp_wait<NSTAGE - 1>();
        __syncthreads();
        uint32_t st = sb + (uint32_t)((i % NSTAGE) * STAGE_BYTES);
        uint32_t aB = st + aOff;
        uint32_t bB = st + bOff;
        #pragma unroll
        for (int ks = 0; ks < 2; ks++) {
            uint32_t ak = aB + ks * 32;
            uint32_t bk = bB + ks * 32;
            uint32_t ah[4][4], bh[4][2];
            #pragma unroll
            for (int mt = 0; mt < 4; mt++) ldsm4(ah[mt], ak + mt * (16 * ROWB));
            #pragma unroll
            for (int nt = 0; nt < 4; nt++) ldsm2(bh[nt], bk + nt * (8 * ROWB));
            #pragma unroll
            for (int mt = 0; mt < 4; mt++)
                #pragma unroll
                for (int nt = 0; nt < 4; nt++)
                    mma16816(acc[mt][nt], ah[mt], bh[nt]);
        }
        __syncthreads();
        if (i + NSTAGE < nch)
            gemm_load_chunk(st, tid, gA, gB, (i + NSTAGE) * KC, K);
        else
            cp_commit();   // keep group count in lockstep
    }

    const int rbase = m0 + wm * 64 + (lane >> 2);
    const int cbase = n0 + wn * 32 + (lane & 3) * 2;
    #pragma unroll
    for (int mt = 0; mt < 4; mt++) {
        #pragma unroll
        for (int nt = 0; nt < 4; nt++) {
            int r = rbase + mt * 16;
            int c = cbase + nt * 8;
            float* p0 = C + (size_t)r * N + c;
            float* p1 = C + (size_t)(r + 8) * N + c;
            float2 v0 = make_float2(acc[mt][nt][0], acc[mt][nt][1]);
            float2 v1 = make_float2(acc[mt][nt][2], acc[mt][nt][3]);
            if (Cres) {
                const float2 r0 = *(const float2*)(Cres + (size_t)r * N + c);
                const float2 r1 = *(const float2*)(Cres + (size_t)(r + 8) * N + c);
                v0.x += r0.x; v0.y += r0.y;
                v1.x += r1.x; v1.y += r1.y;
            }
            *(float2*)p0 = v0;
            *(float2*)p1 = v1;
        }
    }
}

// ================= weight transpose: W[K,N] fp32 -> T[N,K] fp16 =================
__global__ __launch_bounds__(256) void wconv_kernel(
    const float* __restrict__ W, __half* __restrict__ T, int K, int N)
{
    __shared__ float t[32][33];
    int n0 = blockIdx.x * 32, k0 = blockIdx.y * 32;
    int tid = threadIdx.x;
    int tn = tid & 31, tk = tid >> 5;
    #pragma unroll
    for (int i = 0; i < 4; i++)
        t[tk + 8 * i][tn] = W[(size_t)(k0 + tk + 8 * i) * N + n0 + tn];
    __syncthreads();
    #pragma unroll
    for (int i = 0; i < 4; i++) {
        int r = tk + 8 * i, c = tn;
        T[(size_t)(n0 + r) * K + k0 + c] = __float2half(t[c][r]);
    }
}

// ================= RMSNorm -> fp16 =================
__device__ __forceinline__ float warp_red_sum(float v) {
    #pragma unroll
    for (int o = 16; o > 0; o >>= 1) v += __shfl_xor_sync(0xffffffffu, v, o);
    return v;
}

__global__ void rmsnorm_kernel(const float* __restrict__ x, const float* __restrict__ w,
                               __half* __restrict__ out) {
    int row = blockIdx.x;
    int tid = threadIdx.x;
    const float* xr = x + (size_t)row * HID;
    float s = 0.f;
    for (int i = tid; i < HID; i += 256) { float v = xr[i]; s += v * v; }
    __shared__ float red[8];
    __shared__ float s_inv;
    s = warp_red_sum(s);
    if ((tid & 31) == 0) red[tid >> 5] = s;
    __syncthreads();
    if (tid == 0) {
        float t = 0.f;
        #pragma unroll
        for (int i = 0; i < 8; i++) t += red[i];
        s_inv = rsqrtf(t / (float)HID + 1e-6f);
    }
    __syncthreads();
    float inv = s_inv;
    __half* orow = out + (size_t)row * HID;
    for (int i = tid * 2; i < HID; i += 512) {
        float v0 = xr[i] * inv * w[i];
        float v1 = xr[i + 1] * inv * w[i + 1];
        *(__half2*)(orow + i) = __floats2half2_rn(v0, v1);
    }
}

// ================= RoPE: one thread per (s,j), all 12 heads =================
__global__ void rope_kernel(const int* __restrict__ pos_ids) {
    int idx = blockIdx.x * 256 + threadIdx.x;
    if (idx >= SQ * 128) return;
    int j = idx & 127;
    int s = idx >> 7;
    float inv = (float)(1.0 / pow(10000.0, (double)j / 128.0));
    float angf = (float)pos_ids[s] * inv;
    double ang = (double)angf;
    float c = (float)cos(ang);
    float sn = (float)sin(ang);
    #pragma unroll
    for (int h = 0; h < NH; h++) {
        float* b = g_q + (size_t)s * (NH * HD) + h * HD;
        float x0 = b[j], x1 = b[j + 128];
        b[j]       = x0 * c - x1 * sn;
        b[j + 128] = x1 * c + x0 * sn;
    }
    #pragma unroll
    for (int h = 0; h < NKV; h++) {
        float* b = g_k + (size_t)s * (NKV * HD) + h * HD;
        float x0 = b[j], x1 = b[j + 128];
        b[j]       = x0 * c - x1 * sn;
        b[j + 128] = x1 * c + x0 * sn;
    }
}

// ================= Flash attention (fp32), epilogue emits fp16 =================
#define ATTN_SMEM_FLOATS (256 * 64 + 256 * 64 + 64 * 65 + 4 * 64)
#define ATTN_SMEM_BYTES (ATTN_SMEM_FLOATS * sizeof(float))

__global__ __launch_bounds__(128) void attn_kernel(const int* __restrict__ amask) {
    extern __shared__ float sm[];
    float* Qs = sm;
    float* Ks = Qs + 256 * 64;
    float* Ss = Ks + 256 * 64;
    float* mrow = Ss + 64 * 65;
    float* lrow = mrow + 64;
    float* srow = lrow + 64;
    float* mk = srow + 64;

    const int mt = blockIdx.x;
    const int h = blockIdx.y;
    const int m0 = mt * 64;
    const int kvh = h >> 1;
    const int tid = threadIdx.x;
    const int ty = tid >> 3;
    const int tx = tid & 7;

    for (int idx = tid; idx < 64 * 64; idx += 128) {
        int i = idx & 63, d4 = idx >> 6;
        float4 qv = *(const float4*)(g_q + (size_t)(m0 + i) * (NH * HD) + h * HD + d4 * 4);
        Qs[(d4 * 4 + 0) * 64 + i] = qv.x * 0.0625f;
        Qs[(d4 * 4 + 1) * 64 + i] = qv.y * 0.0625f;
        Qs[(d4 * 4 + 2) * 64 + i] = qv.z * 0.0625f;
        Qs[(d4 * 4 + 3) * 64 + i] = qv.w * 0.0625f;
    }
    if (tid < 64) { mrow[tid] = -1e30f; lrow[tid] = 0.f; }
    float acc[4][32];
    #pragma unroll
    for (int a = 0; a < 4; a++)
        #pragma unroll
        for (int w = 0; w < 32; w++) acc[a][w] = 0.f;
    __syncthreads();

    for (int jt = 0; jt <= mt; jt++) {
        int n0 = jt * 64;
        for (int idx = tid; idx < 64 * 64; idx += 128) {
            int c = idx & 63, d4 = idx >> 6;
            float4 kv4 = *(const float4*)(g_k + (size_t)(n0 + c) * (NKV * HD) + kvh * HD + d4 * 4);
            Ks[(d4 * 4 + 0) * 64 + c] = kv4.x;
            Ks[(d4 * 4 + 1) * 64 + c] = kv4.y;
            Ks[(d4 * 4 + 2) * 64 + c] = kv4.z;
            Ks[(d4 * 4 + 3) * 64 + c] = kv4.w;
        }
        if (tid < 64) mk[tid] = (amask[n0 + tid] > 0) ? 0.f : -1e30f;
        __syncthreads();

        float sreg[4][8];
        #pragma unroll
        for (int a = 0; a < 4; a++)
            #pragma unroll
            for (int b = 0; b < 8; b++) sreg[a][b] = 0.f;
        #pragma unroll 8
        for (int k = 0; k < 256; k++) {
            float a0 = Qs[k * 64 + ty];
            float a1 = Qs[k * 64 + ty + 16];
            float a2 = Qs[k * 64 + ty + 32];
            float a3 = Qs[k * 64 + ty + 48];
            float4 b0 = *(float4*)&Ks[k * 64 + tx * 8];
            float4 b1 = *(float4*)&Ks[k * 64 + tx * 8 + 4];
            float bv[8] = {b0.x, b0.y, b0.z, b0.w, b1.x, b1.y, b1.z, b1.w};
            #pragma unroll
            for (int b = 0; b < 8; b++) {
                sreg[0][b] += a0 * bv[b];
                sreg[1][b] += a1 * bv[b];
                sreg[2][b] += a2 * bv[b];
                sreg[3][b] += a3 * bv[b];
            }
        }
        #pragma unroll
        for (int a = 0; a < 4; a++)
            #pragma unroll
            for (int b = 0; b < 8; b++) {
                int i = ty + 16 * a, c = tx * 8 + b;
                float v = sreg[a][b] + mk[c];
                if (jt == mt && (n0 + c) > (m0 + i)) v = -1e30f;
                Ss[c * 65 + i] = v;
            }
        __syncthreads();

        if (tid < 64) {
            int i = tid;
            float mold = mrow[i];
            float mx = mold;
            #pragma unroll 8
            for (int c = 0; c < 64; c++) mx = fmaxf(mx, Ss[c * 65 + i]);
            float sum = 0.f;
            #pragma unroll 8
            for (int c = 0; c < 64; c++) {
                float p = expf(Ss[c * 65 + i] - mx);
                Ss[c * 65 + i] = p;
                sum += p;
            }
            float sc = expf(mold - mx);
            lrow[i] = lrow[i] * sc + sum;
            mrow[i] = mx;
            srow[i] = sc;
        }
        float* Vs = Ks;
        for (int idx = tid; idx < 64 * 64; idx += 128) {
            int c = idx >> 6, d4 = idx & 63;
            *(float4*)&Vs[c * 256 + d4 * 4] =
                *(const float4*)(g_v + (size_t)(n0 + c) * (NKV * HD) + kvh * HD + d4 * 4);
        }
        __syncthreads();

        #pragma unroll
        for (int a = 0; a < 4; a++) {
            float scl = srow[ty + 16 * a];
            #pragma unroll
            for (int w = 0; w < 32; w++) acc[a][w] *= scl;
        }
        #pragma unroll 4
        for (int c = 0; c < 64; c++) {
            float p0 = Ss[c * 65 + ty];
            float p1 = Ss[c * 65 + ty + 16];
            float p2 = Ss[c * 65 + ty + 32];
            float p3 = Ss[c * 65 + ty + 48];
            #pragma unroll
            for (int w = 0; w < 8; w++) {
                float4 vv = *(float4*)&Vs[c * 256 + tx * 4 + w * 32];
                acc[0][w * 4 + 0] += p0 * vv.x; acc[0][w * 4 + 1] += p0 * vv.y;
                acc[0][w * 4 + 2] += p0 * vv.z; acc[0][w * 4 + 3] += p0 * vv.w;
                acc[1][w * 4 + 0] += p1 * vv.x; acc[1][w * 4 + 1] += p1 * vv.y;
                acc[1][w * 4 + 2] += p1 * vv.z; acc[1][w * 4 + 3] += p1 * vv.w;
                acc[2][w * 4 + 0] += p2 * vv.x; acc[2][w * 4 + 1] += p2 * vv.y;
                acc[2][w * 4 + 2] += p2 * vv.z; acc[2][w * 4 + 3] += p2 * vv.w;
                acc[3][w * 4 + 0] += p3 * vv.x; acc[3][w * 4 + 1] += p3 * vv.y;
                acc[3][w * 4 + 2] += p3 * vv.z; acc[3][w * 4 + 3] += p3 * vv.w;
            }
        }
        __syncthreads();
    }

    #pragma unroll
    for (int a = 0; a < 4; a++) {
        int i = ty + 16 * a;
        float invl = 1.f / lrow[i];
        #pragma unroll
        for (int w = 0; w < 8; w++) {
            float o0 = acc[a][w * 4 + 0] * invl;
            float o1 = acc[a][w * 4 + 1] * invl;
            float o2 = acc[a][w * 4 + 2] * invl;
            float o3 = acc[a][w * 4 + 3] * invl;
            size_t off = (size_t)(m0 + i) * (NH * HD) + h * HD + tx * 4 + w * 32;
            *(__half2*)(g_attn + off)     = __floats2half2_rn(o0, o1);
            *(__half2*)(g_attn + off + 2) = __floats2half2_rn(o2, o3);
        }
    }
}

// ================= gelu(gate)*up -> fp16 =================
__device__ __forceinline__ float gelu_tanh(float x) {
    float x3 = x * x * x;
    return 0.5f * x * (1.f + tanhf(0.7978845608028654f * (x + 0.044715f * x3)));
}

__global__ void gelumul_kernel() {
    size_t idx = (size_t)blockIdx.x * 256 + threadIdx.x;
    const size_t n4 = (size_t)SQ * FFI / 4;
    if (idx >= n4) return;
    float4 g = ((const float4*)g_gate)[idx];
    float4 u = ((const float4*)g_up)[idx];
    float m0 = gelu_tanh(g.x) * u.x;
    float m1 = gelu_tanh(g.y) * u.y;
    float m2 = gelu_tanh(g.z) * u.z;
    float m3 = gelu_tanh(g.w) * u.w;
    ((__half2*)g_gact)[idx * 2]     = __floats2half2_rn(m0, m1);
    ((__half2*)g_gact)[idx * 2 + 1] = __floats2half2_rn(m2, m3);
}

// ================= launch =================
template <typename T>
static T* symaddr(const void* sym) {
    void* p = nullptr;
    cudaGetSymbolAddress(&p, sym);
    return (T*)p;
}

extern "C" void kernel_launch(void* const* d_in, const int* in_sizes, int n_in,
                              void* d_out, int out_size) {
    (void)in_sizes; (void)n_in; (void)out_size;
    const float* hs     = (const float*)d_in[0];
    const float* q_w    = (const float*)d_in[1];
    const float* k_w    = (const float*)d_in[2];
    const float* v_w    = (const float*)d_in[3];
    const float* o_w    = (const float*)d_in[4];
    const float* gate_w = (const float*)d_in[5];
    const float* up_w   = (const float*)d_in[6];
    const float* down_w = (const float*)d_in[7];
    const float* ln1_w  = (const float*)d_in[8];
    const float* ln2_w  = (const float*)d_in[9];
    const int*   amask  = (const int*)d_in[10];
    const int*   pos    = (const int*)d_in[11];
    float* out = (float*)d_out;

    __half* xn = symaddr<__half>(g_xn);
    float* q = symaddr<float>(g_q);
    float* k = symaddr<float>(g_k);
    float* v = symaddr<float>(g_v);
    __half* at = symaddr<__half>(g_attn);
    float* h1 = symaddr<float>(g_h1);
    float* gate = symaddr<float>(g_gate);
    float* up = symaddr<float>(g_up);
    __half* ga = symaddr<__half>(g_gact);
    __half* qw = symaddr<__half>(g_qw);
    __half* kw = symaddr<__half>(g_kw);
    __half* vw = symaddr<__half>(g_vw);
    __half* ow = symaddr<__half>(g_ow);
    __half* gw = symaddr<__half>(g_gw);
    __half* uw = symaddr<__half>(g_uw);
    __half* dw = symaddr<__half>(g_dw);

    cudaFuncSetAttribute(mma_gemm_kernel, cudaFuncAttributeMaxDynamicSharedMemorySize, GEMM_SMEM);
    cudaFuncSetAttribute(attn_kernel, cudaFuncAttributeMaxDynamicSharedMemorySize,
                         (int)ATTN_SMEM_BYTES);

    // 0) weight transpose -> fp16 [N,K]
    wconv_kernel<<<dim3(HID / 32, HID / 32), 256>>>(q_w, qw, HID, HID);
    wconv_kernel<<<dim3((NKV * HD) / 32, HID / 32), 256>>>(k_w, kw, HID, NKV * HD);
    wconv_kernel<<<dim3((NKV * HD) / 32, HID / 32), 256>>>(v_w, vw, HID, NKV * HD);
    wconv_kernel<<<dim3(HID / 32, HID / 32), 256>>>(o_w, ow, HID, HID);
    wconv_kernel<<<dim3(FFI / 32, HID / 32), 256>>>(gate_w, gw, HID, FFI);
    wconv_kernel<<<dim3(FFI / 32, HID / 32), 256>>>(up_w, uw, HID, FFI);
    wconv_kernel<<<dim3(HID / 32, FFI / 32), 256>>>(down_w, dw, FFI, HID);

    // 1) input RMSNorm -> fp16
    rmsnorm_kernel<<<SQ, 256>>>(hs, ln1_w, xn);

    // 2) QKV projections (fp16 HMMA)
    mma_gemm_kernel<<<dim3(SQ / 128, HID / 128), 256, GEMM_SMEM>>>(xn, qw, nullptr, q, HID, HID);
    mma_gemm_kernel<<<dim3(SQ / 128, (NKV * HD) / 128), 256, GEMM_SMEM>>>(
        xn, kw, nullptr, k, NKV * HD, HID);
    mma_gemm_kernel<<<dim3(SQ / 128, (NKV * HD) / 128), 256, GEMM_SMEM>>>(
        xn, vw, nullptr, v, NKV * HD, HID);

    // 3) RoPE
    rope_kernel<<<(SQ * 128 + 255) / 256, 256>>>(pos);

    // 4) flash attention (fp32), outputs fp16
    attn_kernel<<<dim3(SQ / 64, NH), 128, ATTN_SMEM_BYTES>>>(amask);

    // 5) O projection + residual
    mma_gemm_kernel<<<dim3(SQ / 128, HID / 128), 256, GEMM_SMEM>>>(at, ow, hs, h1, HID, HID);

    // 6) post-attn RMSNorm -> fp16
    rmsnorm_kernel<<<SQ, 256>>>(h1, ln2_w, xn);

    // 7) MLP
    mma_gemm_kernel<<<dim3(SQ / 128, FFI / 128), 256, GEMM_SMEM>>>(xn, gw, nullptr, gate, FFI, HID);
    mma_gemm_kernel<<<dim3(SQ / 128, FFI / 128), 256, GEMM_SMEM>>>(xn, uw, nullptr, up, FFI, HID);
    {
        size_t n4 = (size_t)SQ * FFI / 4;
        gelumul_kernel<<<(int)((n4 + 255) / 256), 256>>>();
    }
    mma_gemm_kernel<<<dim3(SQ / 128, HID / 128), 256, GEMM_SMEM>>>(ga, dw, h1, out, HID, FFI);
}

// round 7
// speedup vs baseline: 6.6749x; 2.2043x over previous
#include <cuda_runtime.h>
#include <cuda_fp16.h>
#include <math.h>
#include <stdint.h>

#define SQ 4096
#define HID 2048
#define NH 8
#define NKV 4
#define HD 256
#define FFI 8192

// ================= device scratch =================
__device__ __half g_xn[(size_t)SQ * HID];         // rmsnorm output, fp16
__device__ float g_q[(size_t)SQ * NH * HD];       // fp32 q (pre-rope)
__device__ float g_k[(size_t)SQ * NKV * HD];
__device__ float g_v[(size_t)SQ * NKV * HD];
__device__ __half g_qh[(size_t)NH * SQ * HD];     // head-major fp16 q (post-rope, prescaled)
__device__ __half g_kh[(size_t)NKV * SQ * HD];    // head-major fp16 k (post-rope)
__device__ __half g_vt[(size_t)NKV * HD * SQ];    // transposed fp16 v
__device__ __half g_attn[(size_t)SQ * HID];       // attention output, fp16
__device__ float g_h1[(size_t)SQ * HID];
__device__ float g_gate[(size_t)SQ * FFI];
__device__ float g_up[(size_t)SQ * FFI];
__device__ __half g_gact[(size_t)SQ * FFI];
// transposed fp16 weights, layout [N, K]
__device__ __half g_qw[(size_t)HID * HID];
__device__ __half g_kw[(size_t)(NKV * HD) * HID];
__device__ __half g_vw[(size_t)(NKV * HD) * HID];
__device__ __half g_ow[(size_t)HID * HID];
__device__ __half g_gw[(size_t)FFI * HID];
__device__ __half g_uw[(size_t)FFI * HID];
__device__ __half g_dw[(size_t)HID * FFI];

// ================= PTX helpers =================
__device__ __forceinline__ uint32_t smem_u32(const void* p) {
    return (uint32_t)__cvta_generic_to_shared(p);
}
__device__ __forceinline__ void cpasync16(uint32_t s, const void* g) {
    asm volatile("cp.async.cg.shared.global [%0], [%1], 16;" :: "r"(s), "l"(g));
}
__device__ __forceinline__ void cp_commit() { asm volatile("cp.async.commit_group;" ::: "memory"); }
template <int N> __device__ __forceinline__ void cp_wait() {
    asm volatile("cp.async.wait_group %0;" :: "n"(N) : "memory");
}
__device__ __forceinline__ void ldsm4(uint32_t* r, uint32_t a) {
    asm volatile("ldmatrix.sync.aligned.m8n8.x4.shared.b16 {%0,%1,%2,%3}, [%4];"
                 : "=r"(r[0]), "=r"(r[1]), "=r"(r[2]), "=r"(r[3]) : "r"(a));
}
__device__ __forceinline__ void ldsm2(uint32_t* r, uint32_t a) {
    asm volatile("ldmatrix.sync.aligned.m8n8.x2.shared.b16 {%0,%1}, [%2];"
                 : "=r"(r[0]), "=r"(r[1]) : "r"(a));
}
__device__ __forceinline__ void mma16816(float* d, const uint32_t* a, const uint32_t* b) {
    asm volatile(
        "mma.sync.aligned.m16n8k16.row.col.f32.f16.f16.f32 "
        "{%0,%1,%2,%3}, {%4,%5,%6,%7}, {%8,%9}, {%0,%1,%2,%3};"
        : "+f"(d[0]), "+f"(d[1]), "+f"(d[2]), "+f"(d[3])
        : "r"(a[0]), "r"(a[1]), "r"(a[2]), "r"(a[3]), "r"(b[0]), "r"(b[1]));
}
__device__ __forceinline__ uint32_t packh2(float a, float b) {
    __half2 h = __floats2half2_rn(a, b);
    return *(uint32_t*)&h;
}

// ================= fp16 HMMA GEMM (unchanged from R6) =================
#define KC 32
#define ROWB 80
#define B_OFF 10240
#define STAGE_BYTES 20480
#define NSTAGE 4
#define GEMM_SMEM (NSTAGE * STAGE_BYTES)

__device__ __forceinline__ void gemm_load_chunk(
    uint32_t st, int tid, const __half* gA, const __half* gB, int k0, int K)
{
    #pragma unroll
    for (int rep = 0; rep < 2; rep++) {
        int id = tid + rep * 256;
        int r = id >> 2;
        int g = id & 3;
        size_t go = (size_t)r * K + k0 + g * 8;
        uint32_t so = st + (uint32_t)(r * ROWB + g * 16);
        cpasync16(so,         gA + go);
        cpasync16(so + B_OFF, gB + go);
    }
    cp_commit();
}

__global__ __launch_bounds__(256) void mma_gemm_kernel(
    const __half* __restrict__ A, const __half* __restrict__ B,
    const float* __restrict__ Cres, float* __restrict__ C, int N, int K)
{
    extern __shared__ __align__(128) char smem[];
    const uint32_t sb = smem_u32(smem);
    const int tid = threadIdx.x;
    const int lane = tid & 31;
    const int wid = tid >> 5;
    const int wm = wid >> 2;
    const int wn = wid & 3;
    const int m0 = blockIdx.x * 128;
    const int n0 = blockIdx.y * 128;

    const __half* gA = A + (size_t)m0 * K;
    const __half* gB = B + (size_t)n0 * K;
    const int nch = K / KC;

    float acc[4][4][4];
    #pragma unroll
    for (int mt = 0; mt < 4; mt++)
        #pragma unroll
        for (int nt = 0; nt < 4; nt++)
            #pragma unroll
            for (int e = 0; e < 4; e++) acc[mt][nt][e] = 0.f;

    #pragma unroll
    for (int c = 0; c < NSTAGE; c++)
        gemm_load_chunk(sb + c * STAGE_BYTES, tid, gA, gB, c * KC, K);

    const uint32_t aOff = (uint32_t)((wm * 64 + (lane & 15)) * ROWB + ((lane >> 4) * 8) * 2);
    const uint32_t bOff = (uint32_t)(B_OFF + (wn * 32 + (lane & 7)) * ROWB + (((lane >> 3) & 1) * 8) * 2);

    for (int i = 0; i < nch; i++) {
        cp_wait<NSTAGE - 1>();
        __syncthreads();
        uint32_t st = sb + (uint32_t)((i % NSTAGE) * STAGE_BYTES);
        uint32_t aB = st + aOff;
        uint32_t bB = st + bOff;
        #pragma unroll
        for (int ks = 0; ks < 2; ks++) {
            uint32_t ak = aB + ks * 32;
            uint32_t bk = bB + ks * 32;
            uint32_t ah[4][4], bh[4][2];
            #pragma unroll
            for (int mt = 0; mt < 4; mt++) ldsm4(ah[mt], ak + mt * (16 * ROWB));
            #pragma unroll
            for (int nt = 0; nt < 4; nt++) ldsm2(bh[nt], bk + nt * (8 * ROWB));
            #pragma unroll
            for (int mt = 0; mt < 4; mt++)
                #pragma unroll
                for (int nt = 0; nt < 4; nt++)
                    mma16816(acc[mt][nt], ah[mt], bh[nt]);
        }
        __syncthreads();
        if (i + NSTAGE < nch)
            gemm_load_chunk(st, tid, gA, gB, (i + NSTAGE) * KC, K);
        else
            cp_commit();
    }

    const int rbase = m0 + wm * 64 + (lane >> 2);
    const int cbase = n0 + wn * 32 + (lane & 3) * 2;
    #pragma unroll
    for (int mt = 0; mt < 4; mt++) {
        #pragma unroll
        for (int nt = 0; nt < 4; nt++) {
            int r = rbase + mt * 16;
            int c = cbase + nt * 8;
            float* p0 = C + (size_t)r * N + c;
            float* p1 = C + (size_t)(r + 8) * N + c;
            float2 v0 = make_float2(acc[mt][nt][0], acc[mt][nt][1]);
            float2 v1 = make_float2(acc[mt][nt][2], acc[mt][nt][3]);
            if (Cres) {
                const float2 r0 = *(const float2*)(Cres + (size_t)r * N + c);
                const float2 r1 = *(const float2*)(Cres + (size_t)(r + 8) * N + c);
                v0.x += r0.x; v0.y += r0.y;
                v1.x += r1.x; v1.y += r1.y;
            }
            *(float2*)p0 = v0;
            *(float2*)p1 = v1;
        }
    }
}

// ================= weight transpose: W[K,N] fp32 -> T[N,K] fp16 =================
__global__ __launch_bounds__(256) void wconv_kernel(
    const float* __restrict__ W, __half* __restrict__ T, int K, int N)
{
    __shared__ float t[32][33];
    int n0 = blockIdx.x * 32, k0 = blockIdx.y * 32;
    int tid = threadIdx.x;
    int tn = tid & 31, tk = tid >> 5;
    #pragma unroll
    for (int i = 0; i < 4; i++)
        t[tk + 8 * i][tn] = W[(size_t)(k0 + tk + 8 * i) * N + n0 + tn];
    __syncthreads();
    #pragma unroll
    for (int i = 0; i < 4; i++) {
        int r = tk + 8 * i, c = tn;
        T[(size_t)(n0 + r) * K + k0 + c] = __float2half(t[c][r]);
    }
}

// ================= V transpose: g_v fp32 [S][NKV*HD] -> g_vt fp16 [NKV][HD][S] =================
__global__ __launch_bounds__(256) void vtrans_kernel() {
    __shared__ float t[32][33];
    int s0 = blockIdx.x * 32, d0 = blockIdx.y * 32;
    int kvh = blockIdx.z;
    int tid = threadIdx.x;
    int tx = tid & 31, ty = tid >> 5;
    #pragma unroll
    for (int i = 0; i < 4; i++)
        t[ty + 8 * i][tx] = g_v[(size_t)(s0 + ty + 8 * i) * (NKV * HD) + kvh * HD + d0 + tx];
    __syncthreads();
    #pragma unroll
    for (int i = 0; i < 4; i++) {
        int d = ty + 8 * i, s = tx;
        g_vt[(size_t)kvh * HD * SQ + (size_t)(d0 + d) * SQ + s0 + s] = __float2half(t[s][d]);
    }
}

// ================= RMSNorm -> fp16 =================
__device__ __forceinline__ float warp_red_sum(float v) {
    #pragma unroll
    for (int o = 16; o > 0; o >>= 1) v += __shfl_xor_sync(0xffffffffu, v, o);
    return v;
}

__global__ void rmsnorm_kernel(const float* __restrict__ x, const float* __restrict__ w,
                               __half* __restrict__ out) {
    int row = blockIdx.x;
    int tid = threadIdx.x;
    const float* xr = x + (size_t)row * HID;
    float s = 0.f;
    for (int i = tid; i < HID; i += 256) { float v = xr[i]; s += v * v; }
    __shared__ float red[8];
    __shared__ float s_inv;
    s = warp_red_sum(s);
    if ((tid & 31) == 0) red[tid >> 5] = s;
    __syncthreads();
    if (tid == 0) {
        float t = 0.f;
        #pragma unroll
        for (int i = 0; i < 8; i++) t += red[i];
        s_inv = rsqrtf(t / (float)HID + 1e-6f);
    }
    __syncthreads();
    float inv = s_inv;
    __half* orow = out + (size_t)row * HID;
    for (int i = tid * 2; i < HID; i += 512) {
        float v0 = xr[i] * inv * w[i];
        float v1 = xr[i + 1] * inv * w[i + 1];
        *(__half2*)(orow + i) = __floats2half2_rn(v0, v1);
    }
}

// ================= RoPE: fp32 q/k -> fp16 head-major (q prescaled by 1/16) =================
__global__ void rope_kernel(const int* __restrict__ pos_ids) {
    int idx = blockIdx.x * 256 + threadIdx.x;
    if (idx >= SQ * 128) return;
    int j = idx & 127;
    int s = idx >> 7;
    float inv = (float)(1.0 / pow(10000.0, (double)j / 128.0));
    float angf = (float)pos_ids[s] * inv;
    double ang = (double)angf;
    float c = (float)cos(ang);
    float sn = (float)sin(ang);
    #pragma unroll
    for (int h = 0; h < NH; h++) {
        const float* b = g_q + (size_t)s * (NH * HD) + h * HD;
        float x0 = b[j], x1 = b[j + 128];
        __half* o = g_qh + ((size_t)h * SQ + s) * HD;
        o[j]       = __float2half((x0 * c - x1 * sn) * 0.0625f);
        o[j + 128] = __float2half((x1 * c + x0 * sn) * 0.0625f);
    }
    #pragma unroll
    for (int h = 0; h < NKV; h++) {
        const float* b = g_k + (size_t)s * (NKV * HD) + h * HD;
        float x0 = b[j], x1 = b[j + 128];
        __half* o = g_kh + ((size_t)h * SQ + s) * HD;
        o[j]       = __float2half(x0 * c - x1 * sn);
        o[j + 128] = __float2half(x1 * c + x0 * sn);
    }
}

// ================= fp16 HMMA flash attention =================
// 128 queries/CTA (8 warps x 16 rows), 64-key tiles, single-buffer smem.
#define ABM 128
#define ABN 64
#define QROWH 264                 /* halves per Q/K smem row (256 + 8 pad) */
#define VROWH 72                  /* halves per Vt smem row (64 + 8 pad) */
#define ASM_K (ABM * QROWH * 2)                 /* 67584 */
#define ASM_V (ASM_K + ABN * QROWH * 2)         /* 101376 */
#define ASM_MK (ASM_V + HD * VROWH * 2)         /* 138240 */
#define ATTN_SMEM (ASM_MK + ABN * 4)            /* 138496 */

__global__ __launch_bounds__(256, 1) void attn_mma_kernel(const int* __restrict__ amask) {
    extern __shared__ __align__(128) char asmem[];
    const uint32_t sb = smem_u32(asmem);
    float* mk = (float*)(asmem + ASM_MK);
    const int tid = threadIdx.x;
    const int lane = tid & 31;
    const int w = tid >> 5;
    const int bx = blockIdx.x;
    const int h = blockIdx.y;
    const int kvh = h >> 1;
    const int m0 = bx * ABM;
    const int wrow = w * 16;
    const int rq = lane >> 2;
    const int q2 = (lane & 3) * 2;

    const __half* gQ = g_qh + ((size_t)h * SQ + m0) * HD;
    const __half* gK = g_kh + (size_t)kvh * SQ * HD;
    const __half* gVt = g_vt + (size_t)kvh * HD * SQ;

    // load Q tile (persistent): 128 rows x 512B
    for (int c = tid; c < ABM * 32; c += 256) {
        int r = c >> 5, g = c & 31;
        cpasync16(sb + (uint32_t)(r * (QROWH * 2) + g * 16),
                  (const char*)(gQ + (size_t)r * HD) + g * 16);
    }
    cp_commit();

    float accO[32][4];
    #pragma unroll
    for (int vt = 0; vt < 32; vt++)
        #pragma unroll
        for (int e = 0; e < 4; e++) accO[vt][e] = 0.f;
    float mprev0 = -1e30f, mprev1 = -1e30f;
    float lsum0 = 0.f, lsum1 = 0.f;

    const uint32_t aQ = sb + (uint32_t)((wrow + (lane & 15)) * (QROWH * 2) + ((lane >> 4) * 8) * 2);
    const uint32_t bK = sb + (uint32_t)(ASM_K + (lane & 7) * (QROWH * 2) + (((lane >> 3) & 1) * 8) * 2);
    const uint32_t bV = sb + (uint32_t)(ASM_V + (lane & 7) * (VROWH * 2) + (((lane >> 3) & 1) * 8) * 2);

    const int ntiles = 2 * bx + 2;
    for (int jt = 0; jt < ntiles; jt++) {
        const int n0 = jt * ABN;
        __syncthreads();   // previous tile's compute done before overwrite
        for (int c = tid; c < ABN * 32; c += 256) {
            int r = c >> 5, g = c & 31;
            cpasync16(sb + (uint32_t)(ASM_K + r * (QROWH * 2) + g * 16),
                      (const char*)(gK + (size_t)(n0 + r) * HD) + g * 16);
        }
        for (int c = tid; c < HD * 8; c += 256) {
            int r = c >> 3, g = c & 7;
            cpasync16(sb + (uint32_t)(ASM_V + r * (VROWH * 2) + g * 16),
                      (const char*)(gVt + (size_t)r * SQ + n0) + g * 16);
        }
        if (tid < ABN) mk[tid] = (amask[n0 + tid] > 0) ? 0.f : -1e30f;
        cp_commit();
        cp_wait<0>();
        __syncthreads();

        if (n0 > m0 + wrow + 15) continue;   // fully causal-masked for this warp

        // ---- S = Q K^T ----
        float accS[8][4];
        #pragma unroll
        for (int nt = 0; nt < 8; nt++)
            #pragma unroll
            for (int e = 0; e < 4; e++) accS[nt][e] = 0.f;
        #pragma unroll
        for (int kc = 0; kc < 16; kc++) {
            uint32_t a[4];
            ldsm4(a, aQ + kc * 32);
            #pragma unroll
            for (int nt = 0; nt < 8; nt++) {
                uint32_t b[2];
                ldsm2(b, bK + nt * (8 * QROWH * 2) + kc * 32);
                mma16816(accS[nt], a, b);
            }
        }

        // ---- mask ----
        const int grow0 = m0 + wrow + rq;
        const int grow1 = grow0 + 8;
        #pragma unroll
        for (int nt = 0; nt < 8; nt++) {
            int c0 = nt * 8 + q2;
            float k0m = mk[c0], k1m = mk[c0 + 1];
            int gc0 = n0 + c0, gc1 = gc0 + 1;
            accS[nt][0] = (gc0 > grow0) ? -1e30f : accS[nt][0] + k0m;
            accS[nt][1] = (gc1 > grow0) ? -1e30f : accS[nt][1] + k1m;
            accS[nt][2] = (gc0 > grow1) ? -1e30f : accS[nt][2] + k0m;
            accS[nt][3] = (gc1 > grow1) ? -1e30f : accS[nt][3] + k1m;
        }

        // ---- online softmax ----
        float mx0 = -1e30f, mx1 = -1e30f;
        #pragma unroll
        for (int nt = 0; nt < 8; nt++) {
            mx0 = fmaxf(mx0, fmaxf(accS[nt][0], accS[nt][1]));
            mx1 = fmaxf(mx1, fmaxf(accS[nt][2], accS[nt][3]));
        }
        mx0 = fmaxf(mx0, __shfl_xor_sync(0xffffffffu, mx0, 1));
        mx0 = fmaxf(mx0, __shfl_xor_sync(0xffffffffu, mx0, 2));
        mx1 = fmaxf(mx1, __shfl_xor_sync(0xffffffffu, mx1, 1));
        mx1 = fmaxf(mx1, __shfl_xor_sync(0xffffffffu, mx1, 2));
        float nm0 = fmaxf(mprev0, mx0);
        float nm1 = fmaxf(mprev1, mx1);
        float sc0 = __expf(mprev0 - nm0);
        float sc1 = __expf(mprev1 - nm1);
        float s0 = 0.f, s1 = 0.f;
        #pragma unroll
        for (int nt = 0; nt < 8; nt++) {
            float p0 = __expf(accS[nt][0] - nm0);
            float p1 = __expf(accS[nt][1] - nm0);
            float p2 = __expf(accS[nt][2] - nm1);
            float p3 = __expf(accS[nt][3] - nm1);
            accS[nt][0] = p0; accS[nt][1] = p1; accS[nt][2] = p2; accS[nt][3] = p3;
            s0 += p0 + p1; s1 += p2 + p3;
        }
        s0 += __shfl_xor_sync(0xffffffffu, s0, 1);
        s0 += __shfl_xor_sync(0xffffffffu, s0, 2);
        s1 += __shfl_xor_sync(0xffffffffu, s1, 1);
        s1 += __shfl_xor_sync(0xffffffffu, s1, 2);
        lsum0 = lsum0 * sc0 + s0;
        lsum1 = lsum1 * sc1 + s1;
        mprev0 = nm0; mprev1 = nm1;
        #pragma unroll
        for (int vt = 0; vt < 32; vt++) {
            accO[vt][0] *= sc0; accO[vt][1] *= sc0;
            accO[vt][2] *= sc1; accO[vt][3] *= sc1;
        }

        // ---- O += P V ----
        #pragma unroll
        for (int kc2 = 0; kc2 < 4; kc2++) {
            uint32_t a[4];
            a[0] = packh2(accS[2 * kc2][0], accS[2 * kc2][1]);
            a[1] = packh2(accS[2 * kc2][2], accS[2 * kc2][3]);
            a[2] = packh2(accS[2 * kc2 + 1][0], accS[2 * kc2 + 1][1]);
            a[3] = packh2(accS[2 * kc2 + 1][2], accS[2 * kc2 + 1][3]);
            #pragma unroll
            for (int vt = 0; vt < 32; vt++) {
                uint32_t b[2];
                ldsm2(b, bV + vt * (8 * VROWH * 2) + kc2 * 32);
                mma16816(accO[vt], a, b);
            }
        }
    }

    // ---- normalize + write fp16 ----
    float il0 = 1.f / lsum0;
    float il1 = 1.f / lsum1;
    __half* o0 = g_attn + (size_t)(m0 + wrow + rq) * HID + h * HD;
    __half* o1 = g_attn + (size_t)(m0 + wrow + rq + 8) * HID + h * HD;
    #pragma unroll
    for (int vt = 0; vt < 32; vt++) {
        int c = vt * 8 + q2;
        *(__half2*)(o0 + c) = __floats2half2_rn(accO[vt][0] * il0, accO[vt][1] * il0);
        *(__half2*)(o1 + c) = __floats2half2_rn(accO[vt][2] * il1, accO[vt][3] * il1);
    }
}

// ================= gelu(gate)*up -> fp16 =================
__device__ __forceinline__ float gelu_tanh(float x) {
    float x3 = x * x * x;
    return 0.5f * x * (1.f + tanhf(0.7978845608028654f * (x + 0.044715f * x3)));
}

__global__ void gelumul_kernel() {
    size_t idx = (size_t)blockIdx.x * 256 + threadIdx.x;
    const size_t n4 = (size_t)SQ * FFI / 4;
    if (idx >= n4) return;
    float4 g = ((const float4*)g_gate)[idx];
    float4 u = ((const float4*)g_up)[idx];
    float m0 = gelu_tanh(g.x) * u.x;
    float m1 = gelu_tanh(g.y) * u.y;
    float m2 = gelu_tanh(g.z) * u.z;
    float m3 = gelu_tanh(g.w) * u.w;
    ((__half2*)g_gact)[idx * 2]     = __floats2half2_rn(m0, m1);
    ((__half2*)g_gact)[idx * 2 + 1] = __floats2half2_rn(m2, m3);
}

// ================= launch =================
template <typename T>
static T* symaddr(const void* sym) {
    void* p = nullptr;
    cudaGetSymbolAddress(&p, sym);
    return (T*)p;
}

extern "C" void kernel_launch(void* const* d_in, const int* in_sizes, int n_in,
                              void* d_out, int out_size) {
    (void)in_sizes; (void)n_in; (void)out_size;
    const float* hs     = (const float*)d_in[0];
    const float* q_w    = (const float*)d_in[1];
    const float* k_w    = (const float*)d_in[2];
    const float* v_w    = (const float*)d_in[3];
    const float* o_w    = (const float*)d_in[4];
    const float* gate_w = (const float*)d_in[5];
    const float* up_w   = (const float*)d_in[6];
    const float* down_w = (const float*)d_in[7];
    const float* ln1_w  = (const float*)d_in[8];
    const float* ln2_w  = (const float*)d_in[9];
    const int*   amask  = (const int*)d_in[10];
    const int*   pos    = (const int*)d_in[11];
    float* out = (float*)d_out;

    __half* xn = symaddr<__half>(g_xn);
    float* q = symaddr<float>(g_q);
    float* k = symaddr<float>(g_k);
    float* v = symaddr<float>(g_v);
    __half* at = symaddr<__half>(g_attn);
    float* h1 = symaddr<float>(g_h1);
    float* gate = symaddr<float>(g_gate);
    float* up = symaddr<float>(g_up);
    __half* ga = symaddr<__half>(g_gact);
    __half* qw = symaddr<__half>(g_qw);
    __half* kw = symaddr<__half>(g_kw);
    __half* vw = symaddr<__half>(g_vw);
    __half* ow = symaddr<__half>(g_ow);
    __half* gw = symaddr<__half>(g_gw);
    __half* uw = symaddr<__half>(g_uw);
    __half* dw = symaddr<__half>(g_dw);

    cudaFuncSetAttribute(mma_gemm_kernel, cudaFuncAttributeMaxDynamicSharedMemorySize, GEMM_SMEM);
    cudaFuncSetAttribute(attn_mma_kernel, cudaFuncAttributeMaxDynamicSharedMemorySize, ATTN_SMEM);

    // 0) weight transpose -> fp16 [N,K]
    wconv_kernel<<<dim3(HID / 32, HID / 32), 256>>>(q_w, qw, HID, HID);
    wconv_kernel<<<dim3((NKV * HD) / 32, HID / 32), 256>>>(k_w, kw, HID, NKV * HD);
    wconv_kernel<<<dim3((NKV * HD) / 32, HID / 32), 256>>>(v_w, vw, HID, NKV * HD);
    wconv_kernel<<<dim3(HID / 32, HID / 32), 256>>>(o_w, ow, HID, HID);
    wconv_kernel<<<dim3(FFI / 32, HID / 32), 256>>>(gate_w, gw, HID, FFI);
    wconv_kernel<<<dim3(FFI / 32, HID / 32), 256>>>(up_w, uw, HID, FFI);
    wconv_kernel<<<dim3(HID / 32, FFI / 32), 256>>>(down_w, dw, FFI, HID);

    // 1) input RMSNorm -> fp16
    rmsnorm_kernel<<<SQ, 256>>>(hs, ln1_w, xn);

    // 2) QKV projections (fp16 HMMA)
    mma_gemm_kernel<<<dim3(SQ / 128, HID / 128), 256, GEMM_SMEM>>>(xn, qw, nullptr, q, HID, HID);
    mma_gemm_kernel<<<dim3(SQ / 128, (NKV * HD) / 128), 256, GEMM_SMEM>>>(
        xn, kw, nullptr, k, NKV * HD, HID);
    mma_gemm_kernel<<<dim3(SQ / 128, (NKV * HD) / 128), 256, GEMM_SMEM>>>(
        xn, vw, nullptr, v, NKV * HD, HID);

    // 3) RoPE (-> fp16 head-major) + V transpose
    rope_kernel<<<(SQ * 128 + 255) / 256, 256>>>(pos);
    vtrans_kernel<<<dim3(SQ / 32, HD / 32, NKV), 256>>>();

    // 4) fp16 HMMA flash attention
    attn_mma_kernel<<<dim3(SQ / ABM, NH), 256, ATTN_SMEM>>>(amask);

    // 5) O projection + residual
    mma_gemm_kernel<<<dim3(SQ / 128, HID / 128), 256, GEMM_SMEM>>>(at, ow, hs, h1, HID, HID);

    // 6) post-attn RMSNorm -> fp16
    rmsnorm_kernel<<<SQ, 256>>>(h1, ln2_w, xn);

    // 7) MLP
    mma_gemm_kernel<<<dim3(SQ / 128, FFI / 128), 256, GEMM_SMEM>>>(xn, gw, nullptr, gate, FFI, HID);
    mma_gemm_kernel<<<dim3(SQ / 128, FFI / 128), 256, GEMM_SMEM>>>(xn, uw, nullptr, up, FFI, HID);
    {
        size_t n4 = (size_t)SQ * FFI / 4;
        gelumul_kernel<<<(int)((n4 + 255) / 256), 256>>>();
    }
    mma_gemm_kernel<<<dim3(SQ / 128, HID / 128), 256, GEMM_SMEM>>>(ga, dw, h1, out, HID, FFI);
}

// round 8
// speedup vs baseline: 6.8117x; 1.0205x over previous
#include <cuda_runtime.h>
#include <cuda_fp16.h>
#include <math.h>
#include <stdint.h>

#define SQ 4096
#define HID 2048
#define NH 8
#define NKV 4
#define HD 256
#define FFI 8192

// ================= device scratch =================
__device__ __half g_xn[(size_t)SQ * HID];         // rmsnorm output, fp16
__device__ __half g_q16[(size_t)SQ * NH * HD];    // fp16 q (pre-rope)
__device__ __half g_k16[(size_t)SQ * NKV * HD];
__device__ __half g_v16[(size_t)SQ * NKV * HD];
__device__ __half g_qh[(size_t)NH * SQ * HD];     // head-major fp16 q (post-rope, prescaled)
__device__ __half g_kh[(size_t)NKV * SQ * HD];    // head-major fp16 k (post-rope)
__device__ __half g_vt[(size_t)NKV * HD * SQ];    // transposed fp16 v
__device__ __half g_attn[(size_t)SQ * HID];       // attention output, fp16
__device__ float g_h1[(size_t)SQ * HID];
__device__ __half g_gact[(size_t)SQ * FFI];       // gelu(gate)*up, fp16
// transposed fp16 weights, layout [N, K]
__device__ __half g_qw[(size_t)HID * HID];
__device__ __half g_kw[(size_t)(NKV * HD) * HID];
__device__ __half g_vw[(size_t)(NKV * HD) * HID];
__device__ __half g_ow[(size_t)HID * HID];
__device__ __half g_gw[(size_t)FFI * HID];
__device__ __half g_uw[(size_t)FFI * HID];
__device__ __half g_dw[(size_t)HID * FFI];

// ================= PTX helpers =================
__device__ __forceinline__ uint32_t smem_u32(const void* p) {
    return (uint32_t)__cvta_generic_to_shared(p);
}
__device__ __forceinline__ void cpasync16(uint32_t s, const void* g) {
    asm volatile("cp.async.cg.shared.global [%0], [%1], 16;" :: "r"(s), "l"(g));
}
__device__ __forceinline__ void cp_commit() { asm volatile("cp.async.commit_group;" ::: "memory"); }
template <int N> __device__ __forceinline__ void cp_wait() {
    asm volatile("cp.async.wait_group %0;" :: "n"(N) : "memory");
}
__device__ __forceinline__ void ldsm4(uint32_t* r, uint32_t a) {
    asm volatile("ldmatrix.sync.aligned.m8n8.x4.shared.b16 {%0,%1,%2,%3}, [%4];"
                 : "=r"(r[0]), "=r"(r[1]), "=r"(r[2]), "=r"(r[3]) : "r"(a));
}
__device__ __forceinline__ void ldsm2(uint32_t* r, uint32_t a) {
    asm volatile("ldmatrix.sync.aligned.m8n8.x2.shared.b16 {%0,%1}, [%2];"
                 : "=r"(r[0]), "=r"(r[1]) : "r"(a));
}
__device__ __forceinline__ void mma16816(float* d, const uint32_t* a, const uint32_t* b) {
    asm volatile(
        "mma.sync.aligned.m16n8k16.row.col.f32.f16.f16.f32 "
        "{%0,%1,%2,%3}, {%4,%5,%6,%7}, {%8,%9}, {%0,%1,%2,%3};"
        : "+f"(d[0]), "+f"(d[1]), "+f"(d[2]), "+f"(d[3])
        : "r"(a[0]), "r"(a[1]), "r"(a[2]), "r"(a[3]), "r"(b[0]), "r"(b[1]));
}
__device__ __forceinline__ uint32_t packh2(float a, float b) {
    __half2 h = __floats2half2_rn(a, b);
    return *(uint32_t*)&h;
}
__device__ __forceinline__ float gelu_tanh(float x) {
    float x3 = x * x * x;
    return 0.5f * x * (1.f + tanhf(0.7978845608028654f * (x + 0.044715f * x3)));
}

// ================= fp16 HMMA GEMM =================
// C[M,N] = A[M,K](fp16) @ B[N,K](fp16)^T. Tile 128x128, Kc=32, 4-stage cp.async.
// Output: fp32 (+optional residual) if Ch==nullptr, else fp16 to Ch.
#define KC 32
#define ROWB 80
#define B_OFF 10240
#define STAGE_BYTES 20480
#define NSTAGE 4
#define GEMM_SMEM (NSTAGE * STAGE_BYTES)

__device__ __forceinline__ void gemm_load_chunk(
    uint32_t st, int tid, const __half* gA, const __half* gB, int k0, int K)
{
    #pragma unroll
    for (int rep = 0; rep < 2; rep++) {
        int id = tid + rep * 256;
        int r = id >> 2;
        int g = id & 3;
        size_t go = (size_t)r * K + k0 + g * 8;
        uint32_t so = st + (uint32_t)(r * ROWB + g * 16);
        cpasync16(so,         gA + go);
        cpasync16(so + B_OFF, gB + go);
    }
    cp_commit();
}

__global__ __launch_bounds__(256) void mma_gemm_kernel(
    const __half* __restrict__ A, const __half* __restrict__ B,
    const float* __restrict__ Cres, float* __restrict__ C,
    __half* __restrict__ Ch, int N, int K)
{
    extern __shared__ __align__(128) char smem[];
    const uint32_t sb = smem_u32(smem);
    const int tid = threadIdx.x;
    const int lane = tid & 31;
    const int wid = tid >> 5;
    const int wm = wid >> 2;
    const int wn = wid & 3;
    const int m0 = blockIdx.x * 128;
    const int n0 = blockIdx.y * 128;

    const __half* gA = A + (size_t)m0 * K;
    const __half* gB = B + (size_t)n0 * K;
    const int nch = K / KC;

    float acc[4][4][4];
    #pragma unroll
    for (int mt = 0; mt < 4; mt++)
        #pragma unroll
        for (int nt = 0; nt < 4; nt++)
            #pragma unroll
            for (int e = 0; e < 4; e++) acc[mt][nt][e] = 0.f;

    #pragma unroll
    for (int c = 0; c < NSTAGE; c++)
        gemm_load_chunk(sb + c * STAGE_BYTES, tid, gA, gB, c * KC, K);

    const uint32_t aOff = (uint32_t)((wm * 64 + (lane & 15)) * ROWB + ((lane >> 4) * 8) * 2);
    const uint32_t bOff = (uint32_t)(B_OFF + (wn * 32 + (lane & 7)) * ROWB + (((lane >> 3) & 1) * 8) * 2);

    for (int i = 0; i < nch; i++) {
        cp_wait<NSTAGE - 1>();
        __syncthreads();
        uint32_t st = sb + (uint32_t)((i % NSTAGE) * STAGE_BYTES);
        uint32_t aB = st + aOff;
        uint32_t bB = st + bOff;
        #pragma unroll
        for (int ks = 0; ks < 2; ks++) {
            uint32_t ak = aB + ks * 32;
            uint32_t bk = bB + ks * 32;
            uint32_t ah[4][4], bh[4][2];
            #pragma unroll
            for (int mt = 0; mt < 4; mt++) ldsm4(ah[mt], ak + mt * (16 * ROWB));
            #pragma unroll
            for (int nt = 0; nt < 4; nt++) ldsm2(bh[nt], bk + nt * (8 * ROWB));
            #pragma unroll
            for (int mt = 0; mt < 4; mt++)
                #pragma unroll
                for (int nt = 0; nt < 4; nt++)
                    mma16816(acc[mt][nt], ah[mt], bh[nt]);
        }
        __syncthreads();
        if (i + NSTAGE < nch)
            gemm_load_chunk(st, tid, gA, gB, (i + NSTAGE) * KC, K);
        else
            cp_commit();
    }

    const int rbase = m0 + wm * 64 + (lane >> 2);
    const int cbase = n0 + wn * 32 + (lane & 3) * 2;
    #pragma unroll
    for (int mt = 0; mt < 4; mt++) {
        #pragma unroll
        for (int nt = 0; nt < 4; nt++) {
            int r = rbase + mt * 16;
            int c = cbase + nt * 8;
            if (Ch) {
                *(__half2*)(Ch + (size_t)r * N + c) =
                    __floats2half2_rn(acc[mt][nt][0], acc[mt][nt][1]);
                *(__half2*)(Ch + (size_t)(r + 8) * N + c) =
                    __floats2half2_rn(acc[mt][nt][2], acc[mt][nt][3]);
            } else {
                float2 v0 = make_float2(acc[mt][nt][0], acc[mt][nt][1]);
                float2 v1 = make_float2(acc[mt][nt][2], acc[mt][nt][3]);
                if (Cres) {
                    const float2 r0 = *(const float2*)(Cres + (size_t)r * N + c);
                    const float2 r1 = *(const float2*)(Cres + (size_t)(r + 8) * N + c);
                    v0.x += r0.x; v0.y += r0.y;
                    v1.x += r1.x; v1.y += r1.y;
                }
                *(float2*)(C + (size_t)r * N + c) = v0;
                *(float2*)(C + (size_t)(r + 8) * N + c) = v1;
            }
        }
    }
}

// ================= fused gate||up GEMM + gelu(gate)*up -> fp16 =================
// Two B operands staged per chunk; A reused. Output g_gact fp16 [M][FFI].
#define GU_BU_OFF 20480
#define GU_STAGE 30720
#define GU_NSTAGE 4
#define GU_SMEM (GU_NSTAGE * GU_STAGE)

__device__ __forceinline__ void gu_load_chunk(
    uint32_t st, int tid, const __half* gA, const __half* gBg, const __half* gBu,
    int k0, int K)
{
    #pragma unroll
    for (int rep = 0; rep < 2; rep++) {
        int id = tid + rep * 256;
        int r = id >> 2;
        int g = id & 3;
        size_t go = (size_t)r * K + k0 + g * 8;
        uint32_t so = st + (uint32_t)(r * ROWB + g * 16);
        cpasync16(so,             gA + go);
        cpasync16(so + B_OFF,     gBg + go);
        cpasync16(so + GU_BU_OFF, gBu + go);
    }
    cp_commit();
}

__global__ __launch_bounds__(256) void gateup_kernel(
    const __half* __restrict__ A, const __half* __restrict__ Bg,
    const __half* __restrict__ Bu, __half* __restrict__ Out, int N, int K)
{
    extern __shared__ __align__(128) char smem[];
    const uint32_t sb = smem_u32(smem);
    const int tid = threadIdx.x;
    const int lane = tid & 31;
    const int wid = tid >> 5;
    const int wm = wid >> 2;
    const int wn = wid & 3;
    const int m0 = blockIdx.x * 128;
    const int n0 = blockIdx.y * 128;

    const __half* gA = A + (size_t)m0 * K;
    const __half* gBg = Bg + (size_t)n0 * K;
    const __half* gBu = Bu + (size_t)n0 * K;
    const int nch = K / KC;

    float accG[4][4][4], accU[4][4][4];
    #pragma unroll
    for (int mt = 0; mt < 4; mt++)
        #pragma unroll
        for (int nt = 0; nt < 4; nt++)
            #pragma unroll
            for (int e = 0; e < 4; e++) { accG[mt][nt][e] = 0.f; accU[mt][nt][e] = 0.f; }

    #pragma unroll
    for (int c = 0; c < GU_NSTAGE; c++)
        gu_load_chunk(sb + c * GU_STAGE, tid, gA, gBg, gBu, c * KC, K);

    const uint32_t aOff = (uint32_t)((wm * 64 + (lane & 15)) * ROWB + ((lane >> 4) * 8) * 2);
    const uint32_t bOff = (uint32_t)(B_OFF + (wn * 32 + (lane & 7)) * ROWB + (((lane >> 3) & 1) * 8) * 2);

    for (int i = 0; i < nch; i++) {
        cp_wait<GU_NSTAGE - 1>();
        __syncthreads();
        uint32_t st = sb + (uint32_t)((i % GU_NSTAGE) * GU_STAGE);
        uint32_t aB = st + aOff;
        uint32_t bB = st + bOff;
        #pragma unroll
        for (int ks = 0; ks < 2; ks++) {
            uint32_t ak = aB + ks * 32;
            uint32_t bk = bB + ks * 32;
            uint32_t ah[4][4], bg[4][2], bu[4][2];
            #pragma unroll
            for (int mt = 0; mt < 4; mt++) ldsm4(ah[mt], ak + mt * (16 * ROWB));
            #pragma unroll
            for (int nt = 0; nt < 4; nt++) {
                ldsm2(bg[nt], bk + nt * (8 * ROWB));
                ldsm2(bu[nt], bk + (GU_BU_OFF - B_OFF) + nt * (8 * ROWB));
            }
            #pragma unroll
            for (int mt = 0; mt < 4; mt++)
                #pragma unroll
                for (int nt = 0; nt < 4; nt++) {
                    mma16816(accG[mt][nt], ah[mt], bg[nt]);
                    mma16816(accU[mt][nt], ah[mt], bu[nt]);
                }
        }
        __syncthreads();
        if (i + GU_NSTAGE < nch)
            gu_load_chunk(st, tid, gA, gBg, gBu, (i + GU_NSTAGE) * KC, K);
        else
            cp_commit();
    }

    const int rbase = m0 + wm * 64 + (lane >> 2);
    const int cbase = n0 + wn * 32 + (lane & 3) * 2;
    #pragma unroll
    for (int mt = 0; mt < 4; mt++) {
        #pragma unroll
        for (int nt = 0; nt < 4; nt++) {
            int r = rbase + mt * 16;
            int c = cbase + nt * 8;
            *(__half2*)(Out + (size_t)r * N + c) = __floats2half2_rn(
                gelu_tanh(accG[mt][nt][0]) * accU[mt][nt][0],
                gelu_tanh(accG[mt][nt][1]) * accU[mt][nt][1]);
            *(__half2*)(Out + (size_t)(r + 8) * N + c) = __floats2half2_rn(
                gelu_tanh(accG[mt][nt][2]) * accU[mt][nt][2],
                gelu_tanh(accG[mt][nt][3]) * accU[mt][nt][3]);
        }
    }
}

// ================= weight transpose: W[K,N] fp32 -> T[N,K] fp16 =================
__global__ __launch_bounds__(256) void wconv_kernel(
    const float* __restrict__ W, __half* __restrict__ T, int K, int N)
{
    __shared__ float t[32][33];
    int n0 = blockIdx.x * 32, k0 = blockIdx.y * 32;
    int tid = threadIdx.x;
    int tn = tid & 31, tk = tid >> 5;
    #pragma unroll
    for (int i = 0; i < 4; i++)
        t[tk + 8 * i][tn] = W[(size_t)(k0 + tk + 8 * i) * N + n0 + tn];
    __syncthreads();
    #pragma unroll
    for (int i = 0; i < 4; i++) {
        int r = tk + 8 * i, c = tn;
        T[(size_t)(n0 + r) * K + k0 + c] = __float2half(t[c][r]);
    }
}

// ================= V transpose: g_v16 fp16 [S][NKV*HD] -> g_vt fp16 [NKV][HD][S] =================
__global__ __launch_bounds__(256) void vtrans_kernel() {
    __shared__ __half t[32][40];
    int s0 = blockIdx.x * 32, d0 = blockIdx.y * 32;
    int kvh = blockIdx.z;
    int tid = threadIdx.x;
    int tx = tid & 31, ty = tid >> 5;
    #pragma unroll
    for (int i = 0; i < 4; i++)
        t[ty + 8 * i][tx] = g_v16[(size_t)(s0 + ty + 8 * i) * (NKV * HD) + kvh * HD + d0 + tx];
    __syncthreads();
    #pragma unroll
    for (int i = 0; i < 4; i++) {
        int d = ty + 8 * i, s = tx;
        g_vt[(size_t)kvh * HD * SQ + (size_t)(d0 + d) * SQ + s0 + s] = t[s][d];
    }
}

// ================= RMSNorm -> fp16 =================
__device__ __forceinline__ float warp_red_sum(float v) {
    #pragma unroll
    for (int o = 16; o > 0; o >>= 1) v += __shfl_xor_sync(0xffffffffu, v, o);
    return v;
}

__global__ void rmsnorm_kernel(const float* __restrict__ x, const float* __restrict__ w,
                               __half* __restrict__ out) {
    int row = blockIdx.x;
    int tid = threadIdx.x;
    const float* xr = x + (size_t)row * HID;
    float s = 0.f;
    for (int i = tid; i < HID; i += 256) { float v = xr[i]; s += v * v; }
    __shared__ float red[8];
    __shared__ float s_inv;
    s = warp_red_sum(s);
    if ((tid & 31) == 0) red[tid >> 5] = s;
    __syncthreads();
    if (tid == 0) {
        float t = 0.f;
        #pragma unroll
        for (int i = 0; i < 8; i++) t += red[i];
        s_inv = rsqrtf(t / (float)HID + 1e-6f);
    }
    __syncthreads();
    float inv = s_inv;
    __half* orow = out + (size_t)row * HID;
    for (int i = tid * 2; i < HID; i += 512) {
        float v0 = xr[i] * inv * w[i];
        float v1 = xr[i + 1] * inv * w[i + 1];
        *(__half2*)(orow + i) = __floats2half2_rn(v0, v1);
    }
}

// ================= RoPE: fp16 q/k -> fp16 head-major (q prescaled by 1/16) =================
__global__ void rope_kernel(const int* __restrict__ pos_ids) {
    int idx = blockIdx.x * 256 + threadIdx.x;
    if (idx >= SQ * 128) return;
    int j = idx & 127;
    int s = idx >> 7;
    float inv = (float)(1.0 / pow(10000.0, (double)j / 128.0));
    float angf = (float)pos_ids[s] * inv;
    double ang = (double)angf;
    float c = (float)cos(ang);
    float sn = (float)sin(ang);
    #pragma unroll
    for (int h = 0; h < NH; h++) {
        const __half* b = g_q16 + (size_t)s * (NH * HD) + h * HD;
        float x0 = __half2float(b[j]), x1 = __half2float(b[j + 128]);
        __half* o = g_qh + ((size_t)h * SQ + s) * HD;
        o[j]       = __float2half((x0 * c - x1 * sn) * 0.0625f);
        o[j + 128] = __float2half((x1 * c + x0 * sn) * 0.0625f);
    }
    #pragma unroll
    for (int h = 0; h < NKV; h++) {
        const __half* b = g_k16 + (size_t)s * (NKV * HD) + h * HD;
        float x0 = __half2float(b[j]), x1 = __half2float(b[j + 128]);
        __half* o = g_kh + ((size_t)h * SQ + s) * HD;
        o[j]       = __float2half(x0 * c - x1 * sn);
        o[j + 128] = __float2half(x1 * c + x0 * sn);
    }
}

// ================= fp16 HMMA flash attention (unchanged from R7) =================
#define ABM 128
#define ABN 64
#define QROWH 264
#define VROWH 72
#define ASM_K (ABM * QROWH * 2)
#define ASM_V (ASM_K + ABN * QROWH * 2)
#define ASM_MK (ASM_V + HD * VROWH * 2)
#define ATTN_SMEM (ASM_MK + ABN * 4)

__global__ __launch_bounds__(256, 1) void attn_mma_kernel(const int* __restrict__ amask) {
    extern __shared__ __align__(128) char asmem[];
    const uint32_t sb = smem_u32(asmem);
    float* mk = (float*)(asmem + ASM_MK);
    const int tid = threadIdx.x;
    const int lane = tid & 31;
    const int w = tid >> 5;
    const int bx = blockIdx.x;
    const int h = blockIdx.y;
    const int kvh = h >> 1;
    const int m0 = bx * ABM;
    const int wrow = w * 16;
    const int rq = lane >> 2;
    const int q2 = (lane & 3) * 2;

    const __half* gQ = g_qh + ((size_t)h * SQ + m0) * HD;
    const __half* gK = g_kh + (size_t)kvh * SQ * HD;
    const __half* gVt = g_vt + (size_t)kvh * HD * SQ;

    for (int c = tid; c < ABM * 32; c += 256) {
        int r = c >> 5, g = c & 31;
        cpasync16(sb + (uint32_t)(r * (QROWH * 2) + g * 16),
                  (const char*)(gQ + (size_t)r * HD) + g * 16);
    }
    cp_commit();

    float accO[32][4];
    #pragma unroll
    for (int vt = 0; vt < 32; vt++)
        #pragma unroll
        for (int e = 0; e < 4; e++) accO[vt][e] = 0.f;
    float mprev0 = -1e30f, mprev1 = -1e30f;
    float lsum0 = 0.f, lsum1 = 0.f;

    const uint32_t aQ = sb + (uint32_t)((wrow + (lane & 15)) * (QROWH * 2) + ((lane >> 4) * 8) * 2);
    const uint32_t bK = sb + (uint32_t)(ASM_K + (lane & 7) * (QROWH * 2) + (((lane >> 3) & 1) * 8) * 2);
    const uint32_t bV = sb + (uint32_t)(ASM_V + (lane & 7) * (VROWH * 2) + (((lane >> 3) & 1) * 8) * 2);

    const int ntiles = 2 * bx + 2;
    for (int jt = 0; jt < ntiles; jt++) {
        const int n0 = jt * ABN;
        __syncthreads();
        for (int c = tid; c < ABN * 32; c += 256) {
            int r = c >> 5, g = c & 31;
            cpasync16(sb + (uint32_t)(ASM_K + r * (QROWH * 2) + g * 16),
                      (const char*)(gK + (size_t)(n0 + r) * HD) + g * 16);
        }
        for (int c = tid; c < HD * 8; c += 256) {
            int r = c >> 3, g = c & 7;
            cpasync16(sb + (uint32_t)(ASM_V + r * (VROWH * 2) + g * 16),
                      (const char*)(gVt + (size_t)r * SQ + n0) + g * 16);
        }
        if (tid < ABN) mk[tid] = (amask[n0 + tid] > 0) ? 0.f : -1e30f;
        cp_commit();
        cp_wait<0>();
        __syncthreads();

        if (n0 > m0 + wrow + 15) continue;

        float accS[8][4];
        #pragma unroll
        for (int nt = 0; nt < 8; nt++)
            #pragma unroll
            for (int e = 0; e < 4; e++) accS[nt][e] = 0.f;
        #pragma unroll
        for (int kc = 0; kc < 16; kc++) {
            uint32_t a[4];
            ldsm4(a, aQ + kc * 32);
            #pragma unroll
            for (int nt = 0; nt < 8; nt++) {
                uint32_t b[2];
                ldsm2(b, bK + nt * (8 * QROWH * 2) + kc * 32);
                mma16816(accS[nt], a, b);
            }
        }

        const int grow0 = m0 + wrow + rq;
        const int grow1 = grow0 + 8;
        #pragma unroll
        for (int nt = 0; nt < 8; nt++) {
            int c0 = nt * 8 + q2;
            float k0m = mk[c0], k1m = mk[c0 + 1];
            int gc0 = n0 + c0, gc1 = gc0 + 1;
            accS[nt][0] = (gc0 > grow0) ? -1e30f : accS[nt][0] + k0m;
            accS[nt][1] = (gc1 > grow0) ? -1e30f : accS[nt][1] + k1m;
            accS[nt][2] = (gc0 > grow1) ? -1e30f : accS[nt][2] + k0m;
            accS[nt][3] = (gc1 > grow1) ? -1e30f : accS[nt][3] + k1m;
        }

        float mx0 = -1e30f, mx1 = -1e30f;
        #pragma unroll
        for (int nt = 0; nt < 8; nt++) {
            mx0 = fmaxf(mx0, fmaxf(accS[nt][0], accS[nt][1]));
            mx1 = fmaxf(mx1, fmaxf(accS[nt][2], accS[nt][3]));
        }
        mx0 = fmaxf(mx0, __shfl_xor_sync(0xffffffffu, mx0, 1));
        mx0 = fmaxf(mx0, __shfl_xor_sync(0xffffffffu, mx0, 2));
        mx1 = fmaxf(mx1, __shfl_xor_sync(0xffffffffu, mx1, 1));
        mx1 = fmaxf(mx1, __shfl_xor_sync(0xffffffffu, mx1, 2));
        float nm0 = fmaxf(mprev0, mx0);
        float nm1 = fmaxf(mprev1, mx1);
        float sc0 = __expf(mprev0 - nm0);
        float sc1 = __expf(mprev1 - nm1);
        float s0 = 0.f, s1 = 0.f;
        #pragma unroll
        for (int nt = 0; nt < 8; nt++) {
            float p0 = __expf(accS[nt][0] - nm0);
            float p1 = __expf(accS[nt][1] - nm0);
            float p2 = __expf(accS[nt][2] - nm1);
            float p3 = __expf(accS[nt][3] - nm1);
            accS[nt][0] = p0; accS[nt][1] = p1; accS[nt][2] = p2; accS[nt][3] = p3;
            s0 += p0 + p1; s1 += p2 + p3;
        }
        s0 += __shfl_xor_sync(0xffffffffu, s0, 1);
        s0 += __shfl_xor_sync(0xffffffffu, s0, 2);
        s1 += __shfl_xor_sync(0xffffffffu, s1, 1);
        s1 += __shfl_xor_sync(0xffffffffu, s1, 2);
        lsum0 = lsum0 * sc0 + s0;
        lsum1 = lsum1 * sc1 + s1;
        mprev0 = nm0; mprev1 = nm1;
        #pragma unroll
        for (int vt = 0; vt < 32; vt++) {
            accO[vt][0] *= sc0; accO[vt][1] *= sc0;
            accO[vt][2] *= sc1; accO[vt][3] *= sc1;
        }

        #pragma unroll
        for (int kc2 = 0; kc2 < 4; kc2++) {
            uint32_t a[4];
            a[0] = packh2(accS[2 * kc2][0], accS[2 * kc2][1]);
            a[1] = packh2(accS[2 * kc2][2], accS[2 * kc2][3]);
            a[2] = packh2(accS[2 * kc2 + 1][0], accS[2 * kc2 + 1][1]);
            a[3] = packh2(accS[2 * kc2 + 1][2], accS[2 * kc2 + 1][3]);
            #pragma unroll
            for (int vt = 0; vt < 32; vt++) {
                uint32_t b[2];
                ldsm2(b, bV + vt * (8 * VROWH * 2) + kc2 * 32);
                mma16816(accO[vt], a, b);
            }
        }
    }

    float il0 = 1.f / lsum0;
    float il1 = 1.f / lsum1;
    __half* o0 = g_attn + (size_t)(m0 + wrow + rq) * HID + h * HD;
    __half* o1 = g_attn + (size_t)(m0 + wrow + rq + 8) * HID + h * HD;
    #pragma unroll
    for (int vt = 0; vt < 32; vt++) {
        int c = vt * 8 + q2;
        *(__half2*)(o0 + c) = __floats2half2_rn(accO[vt][0] * il0, accO[vt][1] * il0);
        *(__half2*)(o1 + c) = __floats2half2_rn(accO[vt][2] * il1, accO[vt][3] * il1);
    }
}

// ================= launch =================
template <typename T>
static T* symaddr(const void* sym) {
    void* p = nullptr;
    cudaGetSymbolAddress(&p, sym);
    return (T*)p;
}

extern "C" void kernel_launch(void* const* d_in, const int* in_sizes, int n_in,
                              void* d_out, int out_size) {
    (void)in_sizes; (void)n_in; (void)out_size;
    const float* hs     = (const float*)d_in[0];
    const float* q_w    = (const float*)d_in[1];
    const float* k_w    = (const float*)d_in[2];
    const float* v_w    = (const float*)d_in[3];
    const float* o_w    = (const float*)d_in[4];
    const float* gate_w = (const float*)d_in[5];
    const float* up_w   = (const float*)d_in[6];
    const float* down_w = (const float*)d_in[7];
    const float* ln1_w  = (const float*)d_in[8];
    const float* ln2_w  = (const float*)d_in[9];
    const int*   amask  = (const int*)d_in[10];
    const int*   pos    = (const int*)d_in[11];
    float* out = (float*)d_out;

    __half* xn = symaddr<__half>(g_xn);
    __half* q16 = symaddr<__half>(g_q16);
    __half* k16 = symaddr<__half>(g_k16);
    __half* v16 = symaddr<__half>(g_v16);
    __half* at = symaddr<__half>(g_attn);
    float* h1 = symaddr<float>(g_h1);
    __half* ga = symaddr<__half>(g_gact);
    __half* qw = symaddr<__half>(g_qw);
    __half* kw = symaddr<__half>(g_kw);
    __half* vw = symaddr<__half>(g_vw);
    __half* ow = symaddr<__half>(g_ow);
    __half* gw = symaddr<__half>(g_gw);
    __half* uw = symaddr<__half>(g_uw);
    __half* dw = symaddr<__half>(g_dw);

    cudaFuncSetAttribute(mma_gemm_kernel, cudaFuncAttributeMaxDynamicSharedMemorySize, GEMM_SMEM);
    cudaFuncSetAttribute(gateup_kernel, cudaFuncAttributeMaxDynamicSharedMemorySize, GU_SMEM);
    cudaFuncSetAttribute(attn_mma_kernel, cudaFuncAttributeMaxDynamicSharedMemorySize, ATTN_SMEM);

    // 0) weight transpose -> fp16 [N,K]
    wconv_kernel<<<dim3(HID / 32, HID / 32), 256>>>(q_w, qw, HID, HID);
    wconv_kernel<<<dim3((NKV * HD) / 32, HID / 32), 256>>>(k_w, kw, HID, NKV * HD);
    wconv_kernel<<<dim3((NKV * HD) / 32, HID / 32), 256>>>(v_w, vw, HID, NKV * HD);
    wconv_kernel<<<dim3(HID / 32, HID / 32), 256>>>(o_w, ow, HID, HID);
    wconv_kernel<<<dim3(FFI / 32, HID / 32), 256>>>(gate_w, gw, HID, FFI);
    wconv_kernel<<<dim3(FFI / 32, HID / 32), 256>>>(up_w, uw, HID, FFI);
    wconv_kernel<<<dim3(HID / 32, FFI / 32), 256>>>(down_w, dw, FFI, HID);

    // 1) input RMSNorm -> fp16
    rmsnorm_kernel<<<SQ, 256>>>(hs, ln1_w, xn);

    // 2) QKV projections (fp16 out)
    mma_gemm_kernel<<<dim3(SQ / 128, HID / 128), 256, GEMM_SMEM>>>(
        xn, qw, nullptr, nullptr, q16, HID, HID);
    mma_gemm_kernel<<<dim3(SQ / 128, (NKV * HD) / 128), 256, GEMM_SMEM>>>(
        xn, kw, nullptr, nullptr, k16, NKV * HD, HID);
    mma_gemm_kernel<<<dim3(SQ / 128, (NKV * HD) / 128), 256, GEMM_SMEM>>>(
        xn, vw, nullptr, nullptr, v16, NKV * HD, HID);

    // 3) RoPE (-> fp16 head-major) + V transpose
    rope_kernel<<<(SQ * 128 + 255) / 256, 256>>>(pos);
    vtrans_kernel<<<dim3(SQ / 32, HD / 32, NKV), 256>>>();

    // 4) fp16 HMMA flash attention
    attn_mma_kernel<<<dim3(SQ / ABM, NH), 256, ATTN_SMEM>>>(amask);

    // 5) O projection + residual (fp32 out)
    mma_gemm_kernel<<<dim3(SQ / 128, HID / 128), 256, GEMM_SMEM>>>(
        at, ow, hs, h1, nullptr, HID, HID);

    // 6) post-attn RMSNorm -> fp16
    rmsnorm_kernel<<<SQ, 256>>>(h1, ln2_w, xn);

    // 7) MLP: fused gate||up + gelu -> fp16, then down-proj + residual
    gateup_kernel<<<dim3(SQ / 128, FFI / 128), 256, GU_SMEM>>>(xn, gw, uw, ga, FFI, HID);
    mma_gemm_kernel<<<dim3(SQ / 128, HID / 128), 256, GEMM_SMEM>>>(
        ga, dw, h1, out, nullptr, HID, FFI);
}

// round 9
// speedup vs baseline: 7.9982x; 1.1742x over previous
#include <cuda_runtime.h>
#include <cuda_fp16.h>
#include <math.h>
#include <stdint.h>

#define SQ 4096
#define HID 2048
#define NH 8
#define NKV 4
#define HD 256
#define FFI 8192
#define NQKV 4096   /* 2048 q + 1024 k + 1024 v */

// ================= device scratch =================
__device__ __half g_xn[(size_t)SQ * HID];
__device__ __half g_qkv16[(size_t)SQ * NQKV];     // fused qkv output (pre-rope)
__device__ __half g_qh[(size_t)NH * SQ * HD];     // head-major q (post-rope, prescaled)
__device__ __half g_kh[(size_t)NKV * SQ * HD];
__device__ __half g_vt[(size_t)NKV * HD * SQ];
__device__ __half g_attn[(size_t)SQ * HID];
__device__ float g_h1[(size_t)SQ * HID];
__device__ __half g_gact[(size_t)SQ * FFI];
// transposed fp16 weights, layout [N, K]
__device__ __half g_qkvw[(size_t)NQKV * HID];
__device__ __half g_ow[(size_t)HID * HID];
__device__ __half g_gw[(size_t)FFI * HID];
__device__ __half g_uw[(size_t)FFI * HID];
__device__ __half g_dw[(size_t)HID * FFI];

// ================= PTX helpers =================
__device__ __forceinline__ uint32_t smem_u32(const void* p) {
    return (uint32_t)__cvta_generic_to_shared(p);
}
__device__ __forceinline__ void cpasync16(uint32_t s, const void* g) {
    asm volatile("cp.async.cg.shared.global [%0], [%1], 16;" :: "r"(s), "l"(g));
}
__device__ __forceinline__ void cp_commit() { asm volatile("cp.async.commit_group;" ::: "memory"); }
template <int N> __device__ __forceinline__ void cp_wait() {
    asm volatile("cp.async.wait_group %0;" :: "n"(N) : "memory");
}
__device__ __forceinline__ void ldsm4(uint32_t* r, uint32_t a) {
    asm volatile("ldmatrix.sync.aligned.m8n8.x4.shared.b16 {%0,%1,%2,%3}, [%4];"
                 : "=r"(r[0]), "=r"(r[1]), "=r"(r[2]), "=r"(r[3]) : "r"(a));
}
__device__ __forceinline__ void ldsm2(uint32_t* r, uint32_t a) {
    asm volatile("ldmatrix.sync.aligned.m8n8.x2.shared.b16 {%0,%1}, [%2];"
                 : "=r"(r[0]), "=r"(r[1]) : "r"(a));
}
__device__ __forceinline__ void mma16816(float* d, const uint32_t* a, const uint32_t* b) {
    asm volatile(
        "mma.sync.aligned.m16n8k16.row.col.f32.f16.f16.f32 "
        "{%0,%1,%2,%3}, {%4,%5,%6,%7}, {%8,%9}, {%0,%1,%2,%3};"
        : "+f"(d[0]), "+f"(d[1]), "+f"(d[2]), "+f"(d[3])
        : "r"(a[0]), "r"(a[1]), "r"(a[2]), "r"(a[3]), "r"(b[0]), "r"(b[1]));
}
__device__ __forceinline__ uint32_t packh2(float a, float b) {
    __half2 h = __floats2half2_rn(a, b);
    return *(uint32_t*)&h;
}
__device__ __forceinline__ float gelu_tanh(float x) {
    float x3 = x * x * x;
    return 0.5f * x * (1.f + tanhf(0.7978845608028654f * (x + 0.044715f * x3)));
}

// ================= fp16 HMMA GEMM: tile 128x128, Kc=64, 3 stages, B via ldsm4 =================
#define KC 64
#define ROWB 144                      /* 64 halves + 8 pad */
#define AB_STAGE (128 * ROWB)         /* 18432 */
#define STAGE_BYTES (2 * AB_STAGE)    /* 36864: A rows 0-127, B rows 128-255 */
#define NSTAGE 3
#define GEMM_SMEM (NSTAGE * STAGE_BYTES)

__device__ __forceinline__ void gemm_load_chunk(
    uint32_t st, int tid, const __half* gA, const __half* gB, int k0, int K)
{
    #pragma unroll
    for (int rep = 0; rep < 8; rep++) {
        int id = tid + rep * 256;      // 0..2047
        int r = id >> 3;               // 0..255
        int g = id & 7;                // 16B group within 128B row
        const __half* src = (r < 128) ? (gA + (size_t)r * K + k0 + g * 8)
                                      : (gB + (size_t)(r - 128) * K + k0 + g * 8);
        cpasync16(st + (uint32_t)(r * ROWB + g * 16), src);
    }
    cp_commit();
}

__global__ __launch_bounds__(256) void mma_gemm_kernel(
    const __half* __restrict__ A, const __half* __restrict__ B,
    const float* __restrict__ Cres, float* __restrict__ C,
    __half* __restrict__ Ch, int N, int K)
{
    extern __shared__ __align__(128) char smem[];
    const uint32_t sb = smem_u32(smem);
    const int tid = threadIdx.x;
    const int lane = tid & 31;
    const int wid = tid >> 5;
    const int wm = wid >> 2;
    const int wn = wid & 3;
    const int m0 = blockIdx.x * 128;
    const int n0 = blockIdx.y * 128;

    const __half* gA = A + (size_t)m0 * K;
    const __half* gB = B + (size_t)n0 * K;
    const int nch = K / KC;

    float acc[4][4][4];
    #pragma unroll
    for (int mt = 0; mt < 4; mt++)
        #pragma unroll
        for (int nt = 0; nt < 4; nt++)
            #pragma unroll
            for (int e = 0; e < 4; e++) acc[mt][nt][e] = 0.f;

    #pragma unroll
    for (int c = 0; c < NSTAGE; c++)
        gemm_load_chunk(sb + c * STAGE_BYTES, tid, gA, gB, c * KC, K);

    const uint32_t aOff = (uint32_t)((wm * 64 + (lane & 15)) * ROWB + (lane >> 4) * 16);
    const uint32_t bOff = (uint32_t)(AB_STAGE
        + (wn * 32 + (lane & 7) + ((lane >> 4) & 1) * 8) * ROWB
        + ((lane >> 3) & 1) * 16);

    for (int i = 0; i < nch; i++) {
        cp_wait<NSTAGE - 1>();
        __syncthreads();
        uint32_t st = sb + (uint32_t)((i % NSTAGE) * STAGE_BYTES);
        uint32_t aB = st + aOff;
        uint32_t bB = st + bOff;
        #pragma unroll
        for (int ks = 0; ks < 4; ks++) {
            uint32_t ak = aB + ks * 32;
            uint32_t bk = bB + ks * 32;
            uint32_t ah[4][4], bh[2][4];
            #pragma unroll
            for (int mt = 0; mt < 4; mt++) ldsm4(ah[mt], ak + mt * (16 * ROWB));
            #pragma unroll
            for (int np = 0; np < 2; np++) ldsm4(bh[np], bk + np * (16 * ROWB));
            #pragma unroll
            for (int mt = 0; mt < 4; mt++)
                #pragma unroll
                for (int nt = 0; nt < 4; nt++)
                    mma16816(acc[mt][nt], ah[mt], bh[nt >> 1] + (nt & 1) * 2);
        }
        __syncthreads();
        if (i + NSTAGE < nch)
            gemm_load_chunk(st, tid, gA, gB, (i + NSTAGE) * KC, K);
        else
            cp_commit();
    }

    const int rbase = m0 + wm * 64 + (lane >> 2);
    const int cbase = n0 + wn * 32 + (lane & 3) * 2;
    #pragma unroll
    for (int mt = 0; mt < 4; mt++) {
        #pragma unroll
        for (int nt = 0; nt < 4; nt++) {
            int r = rbase + mt * 16;
            int c = cbase + nt * 8;
            if (Ch) {
                *(__half2*)(Ch + (size_t)r * N + c) =
                    __floats2half2_rn(acc[mt][nt][0], acc[mt][nt][1]);
                *(__half2*)(Ch + (size_t)(r + 8) * N + c) =
                    __floats2half2_rn(acc[mt][nt][2], acc[mt][nt][3]);
            } else {
                float2 v0 = make_float2(acc[mt][nt][0], acc[mt][nt][1]);
                float2 v1 = make_float2(acc[mt][nt][2], acc[mt][nt][3]);
                if (Cres) {
                    const float2 r0 = *(const float2*)(Cres + (size_t)r * N + c);
                    const float2 r1 = *(const float2*)(Cres + (size_t)(r + 8) * N + c);
                    v0.x += r0.x; v0.y += r0.y;
                    v1.x += r1.x; v1.y += r1.y;
                }
                *(float2*)(C + (size_t)r * N + c) = v0;
                *(float2*)(C + (size_t)(r + 8) * N + c) = v1;
            }
        }
    }
}

// ================= fused gate||up GEMM + gelu epilogue (Kc=64) =================
#define GU_STAGE (3 * AB_STAGE)       /* A rows 0-127, Bg 128-255, Bu 256-383 */
#define GU_NSTAGE 3
#define GU_SMEM (GU_NSTAGE * GU_STAGE)

__device__ __forceinline__ void gu_load_chunk(
    uint32_t st, int tid, const __half* gA, const __half* gBg, const __half* gBu,
    int k0, int K)
{
    #pragma unroll
    for (int rep = 0; rep < 12; rep++) {
        int id = tid + rep * 256;      // 0..3071
        int r = id >> 3;               // 0..383
        int g = id & 7;
        const __half* src = (r < 128) ? (gA + (size_t)r * K + k0 + g * 8)
                          : (r < 256) ? (gBg + (size_t)(r - 128) * K + k0 + g * 8)
                                      : (gBu + (size_t)(r - 256) * K + k0 + g * 8);
        cpasync16(st + (uint32_t)(r * ROWB + g * 16), src);
    }
    cp_commit();
}

__global__ __launch_bounds__(256) void gateup_kernel(
    const __half* __restrict__ A, const __half* __restrict__ Bg,
    const __half* __restrict__ Bu, __half* __restrict__ Out, int N, int K)
{
    extern __shared__ __align__(128) char smem[];
    const uint32_t sb = smem_u32(smem);
    const int tid = threadIdx.x;
    const int lane = tid & 31;
    const int wid = tid >> 5;
    const int wm = wid >> 2;
    const int wn = wid & 3;
    const int m0 = blockIdx.x * 128;
    const int n0 = blockIdx.y * 128;

    const __half* gA = A + (size_t)m0 * K;
    const __half* gBg = Bg + (size_t)n0 * K;
    const __half* gBu = Bu + (size_t)n0 * K;
    const int nch = K / KC;

    float accG[4][4][4], accU[4][4][4];
    #pragma unroll
    for (int mt = 0; mt < 4; mt++)
        #pragma unroll
        for (int nt = 0; nt < 4; nt++)
            #pragma unroll
            for (int e = 0; e < 4; e++) { accG[mt][nt][e] = 0.f; accU[mt][nt][e] = 0.f; }

    #pragma unroll
    for (int c = 0; c < GU_NSTAGE; c++)
        gu_load_chunk(sb + c * GU_STAGE, tid, gA, gBg, gBu, c * KC, K);

    const uint32_t aOff = (uint32_t)((wm * 64 + (lane & 15)) * ROWB + (lane >> 4) * 16);
    const uint32_t bRow = (uint32_t)((wn * 32 + (lane & 7) + ((lane >> 4) & 1) * 8) * ROWB
                                     + ((lane >> 3) & 1) * 16);

    for (int i = 0; i < nch; i++) {
        cp_wait<GU_NSTAGE - 1>();
        __syncthreads();
        uint32_t st = sb + (uint32_t)((i % GU_NSTAGE) * GU_STAGE);
        uint32_t aB = st + aOff;
        uint32_t gB_ = st + AB_STAGE + bRow;
        uint32_t uB = st + 2 * AB_STAGE + bRow;
        #pragma unroll
        for (int ks = 0; ks < 4; ks++) {
            uint32_t ak = aB + ks * 32;
            uint32_t ah[4][4], bg[2][4], bu[2][4];
            #pragma unroll
            for (int mt = 0; mt < 4; mt++) ldsm4(ah[mt], ak + mt * (16 * ROWB));
            #pragma unroll
            for (int np = 0; np < 2; np++) {
                ldsm4(bg[np], gB_ + np * (16 * ROWB) + ks * 32);
                ldsm4(bu[np], uB + np * (16 * ROWB) + ks * 32);
            }
            #pragma unroll
            for (int mt = 0; mt < 4; mt++)
                #pragma unroll
                for (int nt = 0; nt < 4; nt++) {
                    mma16816(accG[mt][nt], ah[mt], bg[nt >> 1] + (nt & 1) * 2);
                    mma16816(accU[mt][nt], ah[mt], bu[nt >> 1] + (nt & 1) * 2);
                }
        }
        __syncthreads();
        if (i + GU_NSTAGE < nch)
            gu_load_chunk(st, tid, gA, gBg, gBu, (i + GU_NSTAGE) * KC, K);
        else
            cp_commit();
    }

    const int rbase = m0 + wm * 64 + (lane >> 2);
    const int cbase = n0 + wn * 32 + (lane & 3) * 2;
    #pragma unroll
    for (int mt = 0; mt < 4; mt++) {
        #pragma unroll
        for (int nt = 0; nt < 4; nt++) {
            int r = rbase + mt * 16;
            int c = cbase + nt * 8;
            *(__half2*)(Out + (size_t)r * N + c) = __floats2half2_rn(
                gelu_tanh(accG[mt][nt][0]) * accU[mt][nt][0],
                gelu_tanh(accG[mt][nt][1]) * accU[mt][nt][1]);
            *(__half2*)(Out + (size_t)(r + 8) * N + c) = __floats2half2_rn(
                gelu_tanh(accG[mt][nt][2]) * accU[mt][nt][2],
                gelu_tanh(accG[mt][nt][3]) * accU[mt][nt][3]);
        }
    }
}

// ================= weight transpose: W[K,N] fp32 -> T[N,K] fp16 =================
__global__ __launch_bounds__(256) void wconv_kernel(
    const float* __restrict__ W, __half* __restrict__ T, int K, int N)
{
    __shared__ float t[32][33];
    int n0 = blockIdx.x * 32, k0 = blockIdx.y * 32;
    int tid = threadIdx.x;
    int tn = tid & 31, tk = tid >> 5;
    #pragma unroll
    for (int i = 0; i < 4; i++)
        t[tk + 8 * i][tn] = W[(size_t)(k0 + tk + 8 * i) * N + n0 + tn];
    __syncthreads();
    #pragma unroll
    for (int i = 0; i < 4; i++) {
        int r = tk + 8 * i, c = tn;
        T[(size_t)(n0 + r) * K + k0 + c] = __float2half(t[c][r]);
    }
}

// ================= V transpose: g_qkv16 v-cols -> g_vt [NKV][HD][S] =================
__global__ __launch_bounds__(256) void vtrans_kernel() {
    __shared__ __half t[32][40];
    int s0 = blockIdx.x * 32, d0 = blockIdx.y * 32;
    int kvh = blockIdx.z;
    int tid = threadIdx.x;
    int tx = tid & 31, ty = tid >> 5;
    #pragma unroll
    for (int i = 0; i < 4; i++)
        t[ty + 8 * i][tx] =
            g_qkv16[(size_t)(s0 + ty + 8 * i) * NQKV + 3072 + kvh * HD + d0 + tx];
    __syncthreads();
    #pragma unroll
    for (int i = 0; i < 4; i++) {
        int d = ty + 8 * i, s = tx;
        g_vt[(size_t)kvh * HD * SQ + (size_t)(d0 + d) * SQ + s0 + s] = t[s][d];
    }
}

// ================= RMSNorm -> fp16 =================
__device__ __forceinline__ float warp_red_sum(float v) {
    #pragma unroll
    for (int o = 16; o > 0; o >>= 1) v += __shfl_xor_sync(0xffffffffu, v, o);
    return v;
}

__global__ void rmsnorm_kernel(const float* __restrict__ x, const float* __restrict__ w,
                               __half* __restrict__ out) {
    int row = blockIdx.x;
    int tid = threadIdx.x;
    const float* xr = x + (size_t)row * HID;
    float s = 0.f;
    for (int i = tid; i < HID; i += 256) { float v = xr[i]; s += v * v; }
    __shared__ float red[8];
    __shared__ float s_inv;
    s = warp_red_sum(s);
    if ((tid & 31) == 0) red[tid >> 5] = s;
    __syncthreads();
    if (tid == 0) {
        float t = 0.f;
        #pragma unroll
        for (int i = 0; i < 8; i++) t += red[i];
        s_inv = rsqrtf(t / (float)HID + 1e-6f);
    }
    __syncthreads();
    float inv = s_inv;
    __half* orow = out + (size_t)row * HID;
    for (int i = tid * 2; i < HID; i += 512) {
        float v0 = xr[i] * inv * w[i];
        float v1 = xr[i + 1] * inv * w[i + 1];
        *(__half2*)(orow + i) = __floats2half2_rn(v0, v1);
    }
}

// ================= RoPE: g_qkv16 -> fp16 head-major (q prescaled by 1/16) =================
__global__ void rope_kernel(const int* __restrict__ pos_ids) {
    int idx = blockIdx.x * 256 + threadIdx.x;
    if (idx >= SQ * 128) return;
    int j = idx & 127;
    int s = idx >> 7;
    float inv = (float)(1.0 / pow(10000.0, (double)j / 128.0));
    float angf = (float)pos_ids[s] * inv;
    double ang = (double)angf;
    float c = (float)cos(ang);
    float sn = (float)sin(ang);
    #pragma unroll
    for (int h = 0; h < NH; h++) {
        const __half* b = g_qkv16 + (size_t)s * NQKV + h * HD;
        float x0 = __half2float(b[j]), x1 = __half2float(b[j + 128]);
        __half* o = g_qh + ((size_t)h * SQ + s) * HD;
        o[j]       = __float2half((x0 * c - x1 * sn) * 0.0625f);
        o[j + 128] = __float2half((x1 * c + x0 * sn) * 0.0625f);
    }
    #pragma unroll
    for (int h = 0; h < NKV; h++) {
        const __half* b = g_qkv16 + (size_t)s * NQKV + 2048 + h * HD;
        float x0 = __half2float(b[j]), x1 = __half2float(b[j + 128]);
        __half* o = g_kh + ((size_t)h * SQ + s) * HD;
        o[j]       = __float2half(x0 * c - x1 * sn);
        o[j + 128] = __float2half(x1 * c + x0 * sn);
    }
}

// ================= fp16 HMMA flash attention (unchanged from R7) =================
#define ABM 128
#define ABN 64
#define QROWH 264
#define VROWH 72
#define ASM_K (ABM * QROWH * 2)
#define ASM_V (ASM_K + ABN * QROWH * 2)
#define ASM_MK (ASM_V + HD * VROWH * 2)
#define ATTN_SMEM (ASM_MK + ABN * 4)

__global__ __launch_bounds__(256, 1) void attn_mma_kernel(const int* __restrict__ amask) {
    extern __shared__ __align__(128) char asmem[];
    const uint32_t sb = smem_u32(asmem);
    float* mk = (float*)(asmem + ASM_MK);
    const int tid = threadIdx.x;
    const int lane = tid & 31;
    const int w = tid >> 5;
    const int bx = blockIdx.x;
    const int h = blockIdx.y;
    const int kvh = h >> 1;
    const int m0 = bx * ABM;
    const int wrow = w * 16;
    const int rq = lane >> 2;
    const int q2 = (lane & 3) * 2;

    const __half* gQ = g_qh + ((size_t)h * SQ + m0) * HD;
    const __half* gK = g_kh + (size_t)kvh * SQ * HD;
    const __half* gVt = g_vt + (size_t)kvh * HD * SQ;

    for (int c = tid; c < ABM * 32; c += 256) {
        int r = c >> 5, g = c & 31;
        cpasync16(sb + (uint32_t)(r * (QROWH * 2) + g * 16),
                  (const char*)(gQ + (size_t)r * HD) + g * 16);
    }
    cp_commit();

    float accO[32][4];
    #pragma unroll
    for (int vt = 0; vt < 32; vt++)
        #pragma unroll
        for (int e = 0; e < 4; e++) accO[vt][e] = 0.f;
    float mprev0 = -1e30f, mprev1 = -1e30f;
    float lsum0 = 0.f, lsum1 = 0.f;

    const uint32_t aQ = sb + (uint32_t)((wrow + (lane & 15)) * (QROWH * 2) + ((lane >> 4) * 8) * 2);
    const uint32_t bK = sb + (uint32_t)(ASM_K + (lane & 7) * (QROWH * 2) + (((lane >> 3) & 1) * 8) * 2);
    const uint32_t bV = sb + (uint32_t)(ASM_V + (lane & 7) * (VROWH * 2) + (((lane >> 3) & 1) * 8) * 2);

    const int ntiles = 2 * bx + 2;
    for (int jt = 0; jt < ntiles; jt++) {
        const int n0 = jt * ABN;
        __syncthreads();
        for (int c = tid; c < ABN * 32; c += 256) {
            int r = c >> 5, g = c & 31;
            cpasync16(sb + (uint32_t)(ASM_K + r * (QROWH * 2) + g * 16),
                      (const char*)(gK + (size_t)(n0 + r) * HD) + g * 16);
        }
        for (int c = tid; c < HD * 8; c += 256) {
            int r = c >> 3, g = c & 7;
            cpasync16(sb + (uint32_t)(ASM_V + r * (VROWH * 2) + g * 16),
                      (const char*)(gVt + (size_t)r * SQ + n0) + g * 16);
        }
        if (tid < ABN) mk[tid] = (amask[n0 + tid] > 0) ? 0.f : -1e30f;
        cp_commit();
        cp_wait<0>();
        __syncthreads();

        if (n0 > m0 + wrow + 15) continue;

        float accS[8][4];
        #pragma unroll
        for (int nt = 0; nt < 8; nt++)
            #pragma unroll
            for (int e = 0; e < 4; e++) accS[nt][e] = 0.f;
        #pragma unroll
        for (int kc = 0; kc < 16; kc++) {
            uint32_t a[4];
            ldsm4(a, aQ + kc * 32);
            #pragma unroll
            for (int nt = 0; nt < 8; nt++) {
                uint32_t b[2];
                ldsm2(b, bK + nt * (8 * QROWH * 2) + kc * 32);
                mma16816(accS[nt], a, b);
            }
        }

        const int grow0 = m0 + wrow + rq;
        const int grow1 = grow0 + 8;
        #pragma unroll
        for (int nt = 0; nt < 8; nt++) {
            int c0 = nt * 8 + q2;
            float k0m = mk[c0], k1m = mk[c0 + 1];
            int gc0 = n0 + c0, gc1 = gc0 + 1;
            accS[nt][0] = (gc0 > grow0) ? -1e30f : accS[nt][0] + k0m;
            accS[nt][1] = (gc1 > grow0) ? -1e30f : accS[nt][1] + k1m;
            accS[nt][2] = (gc0 > grow1) ? -1e30f : accS[nt][2] + k0m;
            accS[nt][3] = (gc1 > grow1) ? -1e30f : accS[nt][3] + k1m;
        }

        float mx0 = -1e30f, mx1 = -1e30f;
        #pragma unroll
        for (int nt = 0; nt < 8; nt++) {
            mx0 = fmaxf(mx0, fmaxf(accS[nt][0], accS[nt][1]));
            mx1 = fmaxf(mx1, fmaxf(accS[nt][2], accS[nt][3]));
        }
        mx0 = fmaxf(mx0, __shfl_xor_sync(0xffffffffu, mx0, 1));
        mx0 = fmaxf(mx0, __shfl_xor_sync(0xffffffffu, mx0, 2));
        mx1 = fmaxf(mx1, __shfl_xor_sync(0xffffffffu, mx1, 1));
        mx1 = fmaxf(mx1, __shfl_xor_sync(0xffffffffu, mx1, 2));
        float nm0 = fmaxf(mprev0, mx0);
        float nm1 = fmaxf(mprev1, mx1);
        float sc0 = __expf(mprev0 - nm0);
        float sc1 = __expf(mprev1 - nm1);
        float s0 = 0.f, s1 = 0.f;
        #pragma unroll
        for (int nt = 0; nt < 8; nt++) {
            float p0 = __expf(accS[nt][0] - nm0);
            float p1 = __expf(accS[nt][1] - nm0);
            float p2 = __expf(accS[nt][2] - nm1);
            float p3 = __expf(accS[nt][3] - nm1);
            accS[nt][0] = p0; accS[nt][1] = p1; accS[nt][2] = p2; accS[nt][3] = p3;
            s0 += p0 + p1; s1 += p2 + p3;
        }
        s0 += __shfl_xor_sync(0xffffffffu, s0, 1);
        s0 += __shfl_xor_sync(0xffffffffu, s0, 2);
        s1 += __shfl_xor_sync(0xffffffffu, s1, 1);
        s1 += __shfl_xor_sync(0xffffffffu, s1, 2);
        lsum0 = lsum0 * sc0 + s0;
        lsum1 = lsum1 * sc1 + s1;
        mprev0 = nm0; mprev1 = nm1;
        #pragma unroll
        for (int vt = 0; vt < 32; vt++) {
            accO[vt][0] *= sc0; accO[vt][1] *= sc0;
            accO[vt][2] *= sc1; accO[vt][3] *= sc1;
        }

        #pragma unroll
        for (int kc2 = 0; kc2 < 4; kc2++) {
            uint32_t a[4];
            a[0] = packh2(accS[2 * kc2][0], accS[2 * kc2][1]);
            a[1] = packh2(accS[2 * kc2][2], accS[2 * kc2][3]);
            a[2] = packh2(accS[2 * kc2 + 1][0], accS[2 * kc2 + 1][1]);
            a[3] = packh2(accS[2 * kc2 + 1][2], accS[2 * kc2 + 1][3]);
            #pragma unroll
            for (int vt = 0; vt < 32; vt++) {
                uint32_t b[2];
                ldsm2(b, bV + vt * (8 * VROWH * 2) + kc2 * 32);
                mma16816(accO[vt], a, b);
            }
        }
    }

    float il0 = 1.f / lsum0;
    float il1 = 1.f / lsum1;
    __half* o0 = g_attn + (size_t)(m0 + wrow + rq) * HID + h * HD;
    __half* o1 = g_attn + (size_t)(m0 + wrow + rq + 8) * HID + h * HD;
    #pragma unroll
    for (int vt = 0; vt < 32; vt++) {
        int c = vt * 8 + q2;
        *(__half2*)(o0 + c) = __floats2half2_rn(accO[vt][0] * il0, accO[vt][1] * il0);
        *(__half2*)(o1 + c) = __floats2half2_rn(accO[vt][2] * il1, accO[vt][3] * il1);
    }
}

// ================= launch =================
template <typename T>
static T* symaddr(const void* sym) {
    void* p = nullptr;
    cudaGetSymbolAddress(&p, sym);
    return (T*)p;
}

extern "C" void kernel_launch(void* const* d_in, const int* in_sizes, int n_in,
                              void* d_out, int out_size) {
    (void)in_sizes; (void)n_in; (void)out_size;
    const float* hs     = (const float*)d_in[0];
    const float* q_w    = (const float*)d_in[1];
    const float* k_w    = (const float*)d_in[2];
    const float* v_w    = (const float*)d_in[3];
    const float* o_w    = (const float*)d_in[4];
    const float* gate_w = (const float*)d_in[5];
    const float* up_w   = (const float*)d_in[6];
    const float* down_w = (const float*)d_in[7];
    const float* ln1_w  = (const float*)d_in[8];
    const float* ln2_w  = (const float*)d_in[9];
    const int*   amask  = (const int*)d_in[10];
    const int*   pos    = (const int*)d_in[11];
    float* out = (float*)d_out;

    __half* xn = symaddr<__half>(g_xn);
    __half* qkv16 = symaddr<__half>(g_qkv16);
    __half* at = symaddr<__half>(g_attn);
    float* h1 = symaddr<float>(g_h1);
    __half* ga = symaddr<__half>(g_gact);
    __half* qkvw = symaddr<__half>(g_qkvw);
    __half* ow = symaddr<__half>(g_ow);
    __half* gw = symaddr<__half>(g_gw);
    __half* uw = symaddr<__half>(g_uw);
    __half* dw = symaddr<__half>(g_dw);

    cudaFuncSetAttribute(mma_gemm_kernel, cudaFuncAttributeMaxDynamicSharedMemorySize, GEMM_SMEM);
    cudaFuncSetAttribute(gateup_kernel, cudaFuncAttributeMaxDynamicSharedMemorySize, GU_SMEM);
    cudaFuncSetAttribute(attn_mma_kernel, cudaFuncAttributeMaxDynamicSharedMemorySize, ATTN_SMEM);

    // 0) weight transpose -> fp16 [N,K]; q/k/v into one concatenated buffer
    wconv_kernel<<<dim3(HID / 32, HID / 32), 256>>>(q_w, qkvw, HID, HID);
    wconv_kernel<<<dim3((NKV * HD) / 32, HID / 32), 256>>>(
        k_w, qkvw + (size_t)2048 * HID, HID, NKV * HD);
    wconv_kernel<<<dim3((NKV * HD) / 32, HID / 32), 256>>>(
        v_w, qkvw + (size_t)3072 * HID, HID, NKV * HD);
    wconv_kernel<<<dim3(HID / 32, HID / 32), 256>>>(o_w, ow, HID, HID);
    wconv_kernel<<<dim3(FFI / 32, HID / 32), 256>>>(gate_w, gw, HID, FFI);
    wconv_kernel<<<dim3(FFI / 32, HID / 32), 256>>>(up_w, uw, HID, FFI);
    wconv_kernel<<<dim3(HID / 32, FFI / 32), 256>>>(down_w, dw, FFI, HID);

    // 1) input RMSNorm -> fp16
    rmsnorm_kernel<<<SQ, 256>>>(hs, ln1_w, xn);

    // 2) fused QKV projection (fp16 out)
    mma_gemm_kernel<<<dim3(SQ / 128, NQKV / 128), 256, GEMM_SMEM>>>(
        xn, qkvw, nullptr, nullptr, qkv16, NQKV, HID);

    // 3) RoPE (-> fp16 head-major) + V transpose
    rope_kernel<<<(SQ * 128 + 255) / 256, 256>>>(pos);
    vtrans_kernel<<<dim3(SQ / 32, HD / 32, NKV), 256>>>();

    // 4) fp16 HMMA flash attention
    attn_mma_kernel<<<dim3(SQ / ABM, NH), 256, ATTN_SMEM>>>(amask);

    // 5) O projection + residual (fp32 out)
    mma_gemm_kernel<<<dim3(SQ / 128, HID / 128), 256, GEMM_SMEM>>>(
        at, ow, hs, h1, nullptr, HID, HID);

    // 6) post-attn RMSNorm -> fp16
    rmsnorm_kernel<<<SQ, 256>>>(h1, ln2_w, xn);

    // 7) MLP: fused gate||up + gelu -> fp16, then down-proj + residual
    gateup_kernel<<<dim3(SQ / 128, FFI / 128), 256, GU_SMEM>>>(xn, gw, uw, ga, FFI, HID);
    mma_gemm_kernel<<<dim3(SQ / 128, HID / 128), 256, GEMM_SMEM>>>(
        ga, dw, h1, out, nullptr, HID, FFI);
}